// round 6
// baseline (speedup 1.0000x reference)
#include <cuda_runtime.h>
#include <cstdint>
#include <cstddef>

// ---------------- problem constants ----------------
#define S_LEN   4096
#define D_DIM   2048
#define C_DIM   64
#define M_CH    4
#define NC_CH   1024
#define TOPK_N  512
#define NH_N    16
#define DC_N    512
#define NHI_N   4
#define CI_N    64
#define NG_N    4
#define DG_N    512

#define NEG_INF (__int_as_float(0xff800000))

// ---------------- scratch (device globals; no allocation allowed) -------
__device__ float g_ca[S_LEN * C_DIM];
__device__ float g_cb[S_LEN * C_DIM];
__device__ float g_za[S_LEN * C_DIM];
__device__ float g_zb[S_LEN * C_DIM];
__device__ float g_kc[NC_CH * C_DIM];
__device__ float g_cq[S_LEN * DC_N];
__device__ float g_qi[S_LEN * NHI_N * CI_N];
__device__ float g_hw[S_LEN * NHI_N];
__device__ float g_ko[NC_CH * D_DIM];
__device__ float g_kp[NC_CH * CI_N];
__device__ float g_qf[S_LEN * NH_N * C_DIM];
__device__ float g_is[(size_t)S_LEN * NC_CH];
__device__ int   g_ti[S_LEN * TOPK_N];
__device__ float g_ao[S_LEN * NH_N * C_DIM];
__device__ float g_gb[(size_t)S_LEN * NG_N * DG_N];

// ---------------- tf32 helpers ----------------
__device__ __forceinline__ void f2tf32_pair(float v, uint32_t& hi, uint32_t& lo) {
  asm("cvt.rna.tf32.f32 %0, %1;" : "=r"(hi) : "f"(v));
  float r = v - __uint_as_float(hi);
  asm("cvt.rna.tf32.f32 %0, %1;" : "=r"(lo) : "f"(r));
}

__device__ __forceinline__ void mma_tf32(float* c, const uint32_t* a, const uint32_t* b) {
  asm volatile(
      "mma.sync.aligned.m16n8k8.row.col.f32.tf32.tf32.f32 "
      "{%0,%1,%2,%3}, {%4,%5,%6,%7}, {%8,%9}, {%0,%1,%2,%3};"
      : "+f"(c[0]), "+f"(c[1]), "+f"(c[2]), "+f"(c[3])
      : "r"(a[0]), "r"(a[1]), "r"(a[2]), "r"(a[3]), "r"(b[0]), "r"(b[1]));
}

// ========== tensor-core GEMM (tf32 3x split) — CONTINUOUS path only =====
// Used for w_uq / o_down / o_up where ~1e-6 perturbation is harmless.
__global__ __launch_bounds__(256) void tgemm_kernel(
    const float* __restrict__ A, const float* __restrict__ B,
    float* __restrict__ Cc, int K, int lda, int ldb, int ldc,
    long sA, long sB, long sC) {
  A += (long)blockIdx.z * sA;
  B += (long)blockIdx.z * sB;
  Cc += (long)blockIdx.z * sC;

  __shared__ float As[2][16][133];  // [k][row]
  __shared__ float Bs[2][16][132];  // [k][col]

  const int bm = blockIdx.y * 128;
  const int bn = blockIdx.x * 128;
  const int tid = threadIdx.x;
  const int warp = tid >> 5, lane = tid & 31;
  const int wm = warp >> 2, wn = warp & 3;  // 2 x 4 warp grid
  const int g = lane >> 2, t = lane & 3;

  const int arow = tid >> 1, akoff = (tid & 1) * 8;
  const int brow = tid >> 5, bcol = lane * 4;

  const float* Aptr = A + (size_t)(bm + arow) * lda + akoff;
  const float* Bptr = B + (size_t)brow * ldb + bn + bcol;

  float acc[4][4][4];
#pragma unroll
  for (int i = 0; i < 4; i++)
#pragma unroll
    for (int j = 0; j < 4; j++)
#pragma unroll
      for (int r = 0; r < 4; r++) acc[i][j][r] = 0.f;

  {
    float4 av0 = *reinterpret_cast<const float4*>(Aptr);
    float4 av1 = *reinterpret_cast<const float4*>(Aptr + 4);
    float4 bv0 = *reinterpret_cast<const float4*>(Bptr);
    float4 bv1 = *reinterpret_cast<const float4*>(Bptr + (size_t)8 * ldb);
    As[0][akoff + 0][arow] = av0.x;
    As[0][akoff + 1][arow] = av0.y;
    As[0][akoff + 2][arow] = av0.z;
    As[0][akoff + 3][arow] = av0.w;
    As[0][akoff + 4][arow] = av1.x;
    As[0][akoff + 5][arow] = av1.y;
    As[0][akoff + 6][arow] = av1.z;
    As[0][akoff + 7][arow] = av1.w;
    *reinterpret_cast<float4*>(&Bs[0][brow][bcol]) = bv0;
    *reinterpret_cast<float4*>(&Bs[0][brow + 8][bcol]) = bv1;
  }
  __syncthreads();

  int buf = 0;
  for (int k0 = 0; k0 < K; k0 += 16) {
    float4 av0, av1, bv0, bv1;
    const bool more = (k0 + 16 < K);
    if (more) {
      av0 = *reinterpret_cast<const float4*>(Aptr + k0 + 16);
      av1 = *reinterpret_cast<const float4*>(Aptr + k0 + 20);
      bv0 = *reinterpret_cast<const float4*>(Bptr + (size_t)(k0 + 16) * ldb);
      bv1 = *reinterpret_cast<const float4*>(Bptr + (size_t)(k0 + 24) * ldb);
    }

#pragma unroll
    for (int ks = 0; ks < 16; ks += 8) {
      uint32_t bh[4][2], bl[4][2];
#pragma unroll
      for (int ni = 0; ni < 4; ni++) {
        int colB = wn * 32 + ni * 8 + g;
        f2tf32_pair(Bs[buf][ks + t][colB], bh[ni][0], bl[ni][0]);
        f2tf32_pair(Bs[buf][ks + t + 4][colB], bh[ni][1], bl[ni][1]);
      }
#pragma unroll
      for (int mi = 0; mi < 4; mi++) {
        int rowA = wm * 64 + mi * 16 + g;
        uint32_t ah[4], al[4];
        f2tf32_pair(As[buf][ks + t][rowA], ah[0], al[0]);
        f2tf32_pair(As[buf][ks + t][rowA + 8], ah[1], al[1]);
        f2tf32_pair(As[buf][ks + t + 4][rowA], ah[2], al[2]);
        f2tf32_pair(As[buf][ks + t + 4][rowA + 8], ah[3], al[3]);
#pragma unroll
        for (int ni = 0; ni < 4; ni++) {
          mma_tf32(acc[mi][ni], ah, bh[ni]);
          mma_tf32(acc[mi][ni], ah, bl[ni]);
          mma_tf32(acc[mi][ni], al, bh[ni]);
        }
      }
    }

    if (more) {
      int nb = buf ^ 1;
      As[nb][akoff + 0][arow] = av0.x;
      As[nb][akoff + 1][arow] = av0.y;
      As[nb][akoff + 2][arow] = av0.z;
      As[nb][akoff + 3][arow] = av0.w;
      As[nb][akoff + 4][arow] = av1.x;
      As[nb][akoff + 5][arow] = av1.y;
      As[nb][akoff + 6][arow] = av1.z;
      As[nb][akoff + 7][arow] = av1.w;
      *reinterpret_cast<float4*>(&Bs[nb][brow][bcol]) = bv0;
      *reinterpret_cast<float4*>(&Bs[nb][brow + 8][bcol]) = bv1;
      __syncthreads();
      buf = nb;
    }
  }

#pragma unroll
  for (int mi = 0; mi < 4; mi++) {
    int row0 = bm + wm * 64 + mi * 16 + g;
#pragma unroll
    for (int ni = 0; ni < 4; ni++) {
      int col = bn + wn * 32 + ni * 8 + 2 * t;
      *reinterpret_cast<float2*>(Cc + (size_t)row0 * ldc + col) =
          make_float2(acc[mi][ni][0], acc[mi][ni][1]);
      *reinterpret_cast<float2*>(Cc + (size_t)(row0 + 8) * ldc + col) =
          make_float2(acc[mi][ni][2], acc[mi][ni][3]);
    }
  }
}

// ========== fp32 SGEMM (R4-exact) — DISCRETE-feeding path (c_q, q_i) ====
// Bitwise-identical arithmetic to the passing R4 kernel, so top-k
// selections match the reference exactly.
__global__ __launch_bounds__(256, 2) void sgemm_kernel(
    const float* __restrict__ A, const float* __restrict__ B,
    float* __restrict__ Cc, int K, int lda, int ldb, int ldc,
    long sA, long sB, long sC) {
  A += (long)blockIdx.z * sA;
  B += (long)blockIdx.z * sB;
  Cc += (long)blockIdx.z * sC;

  __shared__ float As[2][8][128];
  __shared__ float Bs[2][8][132];
  const int bm = blockIdx.y * 128;
  const int bn = blockIdx.x * 128;
  const int tid = threadIdx.x;
  const int tx = tid & 15, ty = tid >> 4;
  const int arow = tid >> 1, acol = (tid & 1) * 4;
  const int brow = tid >> 5, bcol = (tid & 31) * 4;

  const float* Aptr = A + (size_t)(bm + arow) * lda + acol;
  const float* Bptr = B + (size_t)brow * ldb + bn + bcol;

  float acc[8][8];
#pragma unroll
  for (int i = 0; i < 8; i++)
#pragma unroll
    for (int j = 0; j < 8; j++) acc[i][j] = 0.f;

  {
    float4 av = *reinterpret_cast<const float4*>(Aptr);
    float4 bv = *reinterpret_cast<const float4*>(Bptr);
    As[0][acol + 0][arow] = av.x;
    As[0][acol + 1][arow] = av.y;
    As[0][acol + 2][arow] = av.z;
    As[0][acol + 3][arow] = av.w;
    Bs[0][brow][bcol + 0] = bv.x;
    Bs[0][brow][bcol + 1] = bv.y;
    Bs[0][brow][bcol + 2] = bv.z;
    Bs[0][brow][bcol + 3] = bv.w;
  }
  __syncthreads();

  int buf = 0;
  for (int k0 = 0; k0 < K; k0 += 8) {
    float4 av, bv;
    const bool more = (k0 + 8 < K);
    if (more) {
      av = *reinterpret_cast<const float4*>(Aptr + k0 + 8);
      bv = *reinterpret_cast<const float4*>(Bptr + (size_t)(k0 + 8) * ldb);
    }
#pragma unroll
    for (int kk = 0; kk < 8; kk++) {
      float a[8], b[8];
#pragma unroll
      for (int i = 0; i < 8; i++) a[i] = As[buf][kk][ty * 8 + i];
#pragma unroll
      for (int j = 0; j < 8; j++) b[j] = Bs[buf][kk][tx * 8 + j];
#pragma unroll
      for (int i = 0; i < 8; i++)
#pragma unroll
        for (int j = 0; j < 8; j++) acc[i][j] += a[i] * b[j];
    }
    if (more) {
      int nb = buf ^ 1;
      As[nb][acol + 0][arow] = av.x;
      As[nb][acol + 1][arow] = av.y;
      As[nb][acol + 2][arow] = av.z;
      As[nb][acol + 3][arow] = av.w;
      Bs[nb][brow][bcol + 0] = bv.x;
      Bs[nb][brow][bcol + 1] = bv.y;
      Bs[nb][brow][bcol + 2] = bv.z;
      Bs[nb][brow][bcol + 3] = bv.w;
      __syncthreads();
      buf = nb;
    }
  }

#pragma unroll
  for (int i = 0; i < 8; i++) {
    float* crow = Cc + (size_t)(bm + ty * 8 + i) * ldc + bn + tx * 8;
    *reinterpret_cast<float4*>(crow) = make_float4(acc[i][0], acc[i][1], acc[i][2], acc[i][3]);
    *reinterpret_cast<float4*>(crow + 4) = make_float4(acc[i][4], acc[i][5], acc[i][6], acc[i][7]);
  }
}

// ========== fused narrow projections: 5 independent (A @ B[2048x64]) ====
struct ProjArgs {
  const float* A[5];
  const float* B[5];
  float* Cc[5];
  int M[5];
};

__global__ __launch_bounds__(256, 2) void proj64_kernel(ProjArgs pa) {
  const int mat = blockIdx.x;
  const int bm = blockIdx.y * 128;
  if (bm >= pa.M[mat]) return;
  const float* A = pa.A[mat];
  const float* B = pa.B[mat];
  float* Cc = pa.Cc[mat];

  __shared__ float As[8][128];
  __shared__ float Bs[8][68];
  const int tid = threadIdx.x;
  const int tx = tid & 15, ty = tid >> 4;
  const int arow = tid >> 1, acol = (tid & 1) * 4;
  const int brow = tid >> 4, bcol = (tid & 15) * 4;
  const bool bload = (tid < 128);

  const float* Aptr = A + (size_t)(bm + arow) * D_DIM + acol;
  const float* Bptr = B + (size_t)brow * C_DIM + bcol;

  float acc[8][4];
#pragma unroll
  for (int i = 0; i < 8; i++)
#pragma unroll
    for (int j = 0; j < 4; j++) acc[i][j] = 0.f;

  float4 av = *reinterpret_cast<const float4*>(Aptr);
  float4 bv = bload ? *reinterpret_cast<const float4*>(Bptr) : make_float4(0, 0, 0, 0);

  for (int k0 = 0; k0 < D_DIM; k0 += 8) {
    As[acol + 0][arow] = av.x;
    As[acol + 1][arow] = av.y;
    As[acol + 2][arow] = av.z;
    As[acol + 3][arow] = av.w;
    if (bload) {
      Bs[brow][bcol + 0] = bv.x;
      Bs[brow][bcol + 1] = bv.y;
      Bs[brow][bcol + 2] = bv.z;
      Bs[brow][bcol + 3] = bv.w;
    }
    __syncthreads();

    if (k0 + 8 < D_DIM) {
      av = *reinterpret_cast<const float4*>(Aptr + k0 + 8);
      if (bload) bv = *reinterpret_cast<const float4*>(Bptr + (size_t)(k0 + 8) * C_DIM);
    }

#pragma unroll
    for (int kk = 0; kk < 8; kk++) {
      float a[8], b[4];
#pragma unroll
      for (int i = 0; i < 8; i++) a[i] = As[kk][ty * 8 + i];
#pragma unroll
      for (int j = 0; j < 4; j++) b[j] = Bs[kk][tx * 4 + j];
#pragma unroll
      for (int i = 0; i < 8; i++)
#pragma unroll
        for (int j = 0; j < 4; j++) acc[i][j] += a[i] * b[j];
    }
    __syncthreads();
  }

#pragma unroll
  for (int i = 0; i < 8; i++) {
    float* crow = Cc + (size_t)(bm + ty * 8 + i) * C_DIM + tx * 4;
    *reinterpret_cast<float4*>(crow) = make_float4(acc[i][0], acc[i][1], acc[i][2], acc[i][3]);
  }
}

// ========== hw = x @ w_w [2048x4]: one warp per row ====================
__global__ void hw_kernel(const float* __restrict__ x, const float* __restrict__ w_w) {
  int warp = (blockIdx.x * blockDim.x + threadIdx.x) >> 5;
  int lane = threadIdx.x & 31;
  if (warp >= S_LEN) return;
  const float4* xr = reinterpret_cast<const float4*>(x + (size_t)warp * D_DIM);
  const float4* wr = reinterpret_cast<const float4*>(w_w);
  float d0 = 0.f, d1 = 0.f, d2 = 0.f, d3 = 0.f;
  for (int i = lane; i < D_DIM / 4; i += 32) {
    float4 xv = xr[i];
    float4 w0 = wr[i * 4 + 0];
    float4 w1 = wr[i * 4 + 1];
    float4 w2 = wr[i * 4 + 2];
    float4 w3 = wr[i * 4 + 3];
    d0 += xv.x * w0.x + xv.y * w1.x + xv.z * w2.x + xv.w * w3.x;
    d1 += xv.x * w0.y + xv.y * w1.y + xv.z * w2.y + xv.w * w3.y;
    d2 += xv.x * w0.z + xv.y * w1.z + xv.z * w2.z + xv.w * w3.z;
    d3 += xv.x * w0.w + xv.y * w1.w + xv.z * w2.w + xv.w * w3.w;
  }
#pragma unroll
  for (int off = 16; off > 0; off >>= 1) {
    d0 += __shfl_down_sync(0xffffffffu, d0, off);
    d1 += __shfl_down_sync(0xffffffffu, d1, off);
    d2 += __shfl_down_sync(0xffffffffu, d2, off);
    d3 += __shfl_down_sync(0xffffffffu, d3, off);
  }
  if (lane == 0) {
    g_hw[warp * 4 + 0] = d0;
    g_hw[warp * 4 + 1] = d1;
    g_hw[warp * 4 + 2] = d2;
    g_hw[warp * 4 + 3] = d3;
  }
}

// ---------------- k_orig = mean over the M=4 tokens of each chunk -------
__global__ void kmean_kernel(const float* __restrict__ x) {
  int idx = blockIdx.x * 256 + threadIdx.x;
  if (idx >= NC_CH * D_DIM) return;
  int nc = idx / D_DIM, d = idx - nc * D_DIM;
  const float* p = x + (size_t)nc * 4 * D_DIM + d;
  g_ko[idx] = 0.25f * (p[0] + p[D_DIM] + p[2 * D_DIM] + p[3 * D_DIM]);
}

// ------------- compression softmax (over 8 candidates) + LayerNorm ------
__global__ void compress_kernel(const float* __restrict__ b_a,
                                const float* __restrict__ b_b,
                                const float* __restrict__ kvn_w,
                                const float* __restrict__ kvn_b) {
  int nc = blockIdx.x;
  int c = threadIdx.x;  // 64
  float lg[8], val[8];
#pragma unroll
  for (int m = 0; m < 4; m++) {
    int cur = (nc * 4 + m) * 64 + c;
    lg[4 + m] = g_za[cur] + b_a[m * 64 + c];
    val[4 + m] = g_ca[cur];
    if (nc > 0) {
      int prev = ((nc - 1) * 4 + m) * 64 + c;
      lg[m] = g_zb[prev] + b_b[m * 64 + c];
      val[m] = g_cb[prev];
    } else {
      lg[m] = -1e30f + b_b[m * 64 + c];
      val[m] = 0.f;
    }
  }
  float mx = lg[0];
#pragma unroll
  for (int i = 1; i < 8; i++) mx = fmaxf(mx, lg[i]);
  float se = 0.f, comp = 0.f;
#pragma unroll
  for (int i = 0; i < 8; i++) {
    float e = expf(lg[i] - mx);
    se += e;
    comp += e * val[i];
  }
  comp /= se;

  __shared__ float red[64];
  red[c] = comp;
  __syncthreads();
  for (int off = 32; off > 0; off >>= 1) {
    if (c < off) red[c] += red[c + off];
    __syncthreads();
  }
  float mu = red[0] * (1.f / 64.f);
  __syncthreads();
  float dv = comp - mu;
  red[c] = dv * dv;
  __syncthreads();
  for (int off = 32; off > 0; off >>= 1) {
    if (c < off) red[c] += red[c + off];
    __syncthreads();
  }
  float var = red[0] * (1.f / 64.f);
  g_kc[nc * 64 + c] = dv * rsqrtf(var + 1e-6f) * kvn_w[c] + kvn_b[c];
}

// ------------- per-(s,h) LayerNorm then RoPE on last 32 channels --------
__global__ void qln_rope_kernel(const float* __restrict__ qn_w,
                                const float* __restrict__ qn_b) {
  int s = blockIdx.x;
  int c = threadIdx.x;  // 64
  int h = threadIdx.y;  // 16
  float v = g_qf[(size_t)s * 1024 + h * 64 + c];
  __shared__ float red[16][64];
  __shared__ float lnb[16][65];
  red[h][c] = v;
  __syncthreads();
  for (int off = 32; off > 0; off >>= 1) {
    if (c < off) red[h][c] += red[h][c + off];
    __syncthreads();
  }
  float mu = red[h][0] * (1.f / 64.f);
  __syncthreads();
  float dv = v - mu;
  red[h][c] = dv * dv;
  __syncthreads();
  for (int off = 32; off > 0; off >>= 1) {
    if (c < off) red[h][c] += red[h][c + off];
    __syncthreads();
  }
  float var = red[h][0] * (1.f / 64.f);
  float ln = dv * rsqrtf(var + 1e-6f) * qn_w[c] + qn_b[c];
  lnb[h][c] = ln;
  __syncthreads();
  float outv;
  if (c < 32) {
    outv = ln;
  } else {
    int j = (c - 32) >> 1;
    float inv = exp2f(-(float)j * 0.830482023722f);  // 10000^(-j/16)
    float ang = (float)s * inv;
    float cs = cosf(ang), sn = sinf(ang);
    float x0 = lnb[h][32 + 2 * j], x1 = lnb[h][32 + 2 * j + 1];
    outv = ((c & 1) == 0) ? (x0 * cs - x1 * sn) : (x0 * sn + x1 * cs);
  }
  g_qf[(size_t)s * 1024 + h * 64 + c] = outv;
}

// ------------- indexer scores: relu(q_i . k_proj) weighted by hw --------
__global__ void iscore_kernel() {
  int s = blockIdx.x;
  __shared__ float qs[256];
  __shared__ float ws[4];
  int tid = threadIdx.x;  // 256
  qs[tid] = g_qi[(size_t)s * 256 + tid];
  if (tid < 4) ws[tid] = g_hw[s * 4 + tid];
  __syncthreads();
  const float4* qs4 = reinterpret_cast<const float4*>(qs);
  for (int k = tid; k < NC_CH; k += 256) {
    const float4* kr = reinterpret_cast<const float4*>(g_kp + k * 64);
    float d0 = 0.f, d1 = 0.f, d2 = 0.f, d3 = 0.f;
#pragma unroll
    for (int c4 = 0; c4 < 16; c4++) {
      float4 kv = kr[c4];
      float4 q0 = qs4[c4];
      float4 q1 = qs4[16 + c4];
      float4 q2 = qs4[32 + c4];
      float4 q3 = qs4[48 + c4];
      d0 += q0.x * kv.x + q0.y * kv.y + q0.z * kv.z + q0.w * kv.w;
      d1 += q1.x * kv.x + q1.y * kv.y + q1.z * kv.z + q1.w * kv.w;
      d2 += q2.x * kv.x + q2.y * kv.y + q2.z * kv.z + q2.w * kv.w;
      d3 += q3.x * kv.x + q3.y * kv.y + q3.z * kv.z + q3.w * kv.w;
    }
    float sc = fmaxf(d0, 0.f) * ws[0] + fmaxf(d1, 0.f) * ws[1] +
               fmaxf(d2, 0.f) * ws[2] + fmaxf(d3, 0.f) * ws[3];
    g_is[(size_t)s * NC_CH + k] = (k < s) ? sc : NEG_INF;
  }
}

// ------------- exact top-512: bitonic sort by (value desc, index asc) ---
__global__ __launch_bounds__(512) void topk_kernel() {
  int s = blockIdx.x, tid = threadIdx.x;  // 512
  __shared__ float v[1024];
  __shared__ int ix[1024];
  v[tid] = g_is[(size_t)s * 1024 + tid];
  ix[tid] = tid;
  v[tid + 512] = g_is[(size_t)s * 1024 + tid + 512];
  ix[tid + 512] = tid + 512;
  __syncthreads();
  for (int k = 2; k <= 1024; k <<= 1) {
    for (int j = k >> 1; j > 0; j >>= 1) {
      for (int t = tid; t < 1024; t += 512) {
        int p = t ^ j;
        if (p > t) {
          float va = v[t], vb = v[p];
          int ia = ix[t], ib = ix[p];
          bool before = (va > vb) || (va == vb && ia < ib);
          bool dir = ((t & k) == 0);
          if (before != dir) {
            v[t] = vb; v[p] = va;
            ix[t] = ib; ix[p] = ia;
          }
        }
      }
      __syncthreads();
    }
  }
  g_ti[(size_t)s * 512 + tid] = ix[tid];
}

// ------------- gathered sparse attention (4 quarters of 128 chunks) -----
__global__ __launch_bounds__(256) void attn_kernel(const float* __restrict__ sink) {
  const int s = blockIdx.x, tid = threadIdx.x;  // 256
  __shared__ float qs[1024];
  __shared__ float Ks[128][68];
  __shared__ float ew[16][128];
  __shared__ float denom[16];

#pragma unroll
  for (int i = 0; i < 4; i++) qs[tid + 256 * i] = g_qf[(size_t)s * 1024 + tid + 256 * i];
  if (tid < 16) denom[tid] = __expf(sink[tid]);
  __syncthreads();

  const int c = tid & 63, g = tid >> 6;
  float acc0 = 0.f, acc1 = 0.f, acc2 = 0.f, acc3 = 0.f;
  const float4* qs4 = reinterpret_cast<const float4*>(qs);
  const int* trow = g_ti + (size_t)s * 512;

  for (int qtr = 0; qtr < 4; qtr++) {
    if (qtr) __syncthreads();

    {
      int j = tid >> 1, p = tid & 1;
      int ck = trow[qtr * 128 + j];
      const float4* src = reinterpret_cast<const float4*>(g_kc + ck * 64);
      float4* dst = reinterpret_cast<float4*>(&Ks[j][0]);
#pragma unroll
      for (int q = 0; q < 8; q++) dst[p + 2 * q] = src[p + 2 * q];
    }
    __syncthreads();

    {
      int kk = tid >> 1, hh = (tid & 1) * 8;
      int ck = trow[qtr * 128 + kk];
      bool valid = (s < ck * 4);
      const float4* kr = reinterpret_cast<const float4*>(&Ks[kk][0]);
      float d[8];
#pragma unroll
      for (int h = 0; h < 8; h++) d[h] = 0.f;
#pragma unroll
      for (int c4 = 0; c4 < 16; c4++) {
        float4 kv = kr[c4];
#pragma unroll
        for (int h = 0; h < 8; h++) {
          float4 qv = qs4[(hh + h) * 16 + c4];
          d[h] += qv.x * kv.x + qv.y * kv.y + qv.z * kv.z + qv.w * kv.w;
        }
      }
#pragma unroll
      for (int h = 0; h < 8; h++) ew[hh + h][kk] = valid ? __expf(d[h] * 0.125f) : 0.f;
    }
    __syncthreads();

    {
      int h = tid >> 4, seg = tid & 15;
      float p = 0.f;
#pragma unroll
      for (int k = 0; k < 8; k++) p += ew[h][seg * 8 + k];
#pragma unroll
      for (int off = 8; off > 0; off >>= 1) p += __shfl_down_sync(0xffffffffu, p, off);
      if (seg == 0) denom[h] += p;
    }

    for (int k = 0; k < 128; k++) {
      float kv = Ks[k][c];
      acc0 += ew[g][k] * kv;
      acc1 += ew[g + 4][k] * kv;
      acc2 += ew[g + 8][k] * kv;
      acc3 += ew[g + 12][k] * kv;
    }
  }
  __syncthreads();

  g_ao[(size_t)s * 1024 + (g) * 64 + c] = acc0 / denom[g];
  g_ao[(size_t)s * 1024 + (g + 4) * 64 + c] = acc1 / denom[g + 4];
  g_ao[(size_t)s * 1024 + (g + 8) * 64 + c] = acc2 / denom[g + 8];
  g_ao[(size_t)s * 1024 + (g + 12) * 64 + c] = acc3 / denom[g + 12];
}

// ---------------------------- launcher ----------------------------------
extern "C" void kernel_launch(void* const* d_in, const int* in_sizes, int n_in,
                              void* d_out, int out_size) {
  (void)in_sizes; (void)n_in; (void)out_size;
  const float* x      = (const float*)d_in[0];
  const float* w_kva  = (const float*)d_in[1];
  const float* w_kvb  = (const float*)d_in[2];
  const float* w_za   = (const float*)d_in[3];
  const float* w_zb   = (const float*)d_in[4];
  const float* b_a    = (const float*)d_in[5];
  const float* b_b    = (const float*)d_in[6];
  const float* w_dq   = (const float*)d_in[7];
  const float* w_iuq  = (const float*)d_in[8];
  const float* w_w    = (const float*)d_in[9];
  const float* w_k    = (const float*)d_in[10];
  const float* w_uq   = (const float*)d_in[11];
  const float* o_down = (const float*)d_in[12];
  const float* o_up   = (const float*)d_in[13];
  const float* kvn_w  = (const float*)d_in[14];
  const float* kvn_b  = (const float*)d_in[15];
  const float* qn_w   = (const float*)d_in[16];
  const float* qn_b   = (const float*)d_in[17];
  const float* sink   = (const float*)d_in[18];
  float* out = (float*)d_out;

  void *p_ca, *p_cb, *p_za, *p_zb, *p_cq, *p_qi, *p_ko, *p_kp, *p_qf, *p_ao, *p_gb;
  cudaGetSymbolAddress(&p_ca, g_ca);
  cudaGetSymbolAddress(&p_cb, g_cb);
  cudaGetSymbolAddress(&p_za, g_za);
  cudaGetSymbolAddress(&p_zb, g_zb);
  cudaGetSymbolAddress(&p_cq, g_cq);
  cudaGetSymbolAddress(&p_qi, g_qi);
  cudaGetSymbolAddress(&p_ko, g_ko);
  cudaGetSymbolAddress(&p_kp, g_kp);
  cudaGetSymbolAddress(&p_qf, g_qf);
  cudaGetSymbolAddress(&p_ao, g_ao);
  cudaGetSymbolAddress(&p_gb, g_gb);

  auto grid2 = [](int M, int N) { return dim3((unsigned)(N / 128), (unsigned)(M / 128), 1u); };

  // chunk means first (feeds k_proj inside fused projections)
  kmean_kernel<<<(NC_CH * D_DIM + 255) / 256, 256>>>(x);

  // fused narrow projections
  ProjArgs pa;
  pa.A[0] = x;     pa.B[0] = w_kva; pa.Cc[0] = (float*)p_ca; pa.M[0] = S_LEN;
  pa.A[1] = x;     pa.B[1] = w_kvb; pa.Cc[1] = (float*)p_cb; pa.M[1] = S_LEN;
  pa.A[2] = x;     pa.B[2] = w_za;  pa.Cc[2] = (float*)p_za; pa.M[2] = S_LEN;
  pa.A[3] = x;     pa.B[3] = w_zb;  pa.Cc[3] = (float*)p_zb; pa.M[3] = S_LEN;
  pa.A[4] = (const float*)p_ko; pa.B[4] = w_k; pa.Cc[4] = (float*)p_kp; pa.M[4] = NC_CH;
  proj64_kernel<<<dim3(5, S_LEN / 128), 256>>>(pa);

  // hw = x @ w_w
  hw_kernel<<<S_LEN / 8, 256>>>(x, w_w);

  // c_q = x @ w_dq  (fp32 — feeds the discrete top-k path)
  sgemm_kernel<<<grid2(S_LEN, DC_N), 256>>>(x, w_dq, (float*)p_cq, D_DIM, D_DIM, DC_N, DC_N, 0, 0, 0);

  // chunk compression + LN(kc)
  compress_kernel<<<NC_CH, 64>>>(b_a, b_b, kvn_w, kvn_b);

  // indexer path (fp32 — discrete)
  sgemm_kernel<<<grid2(S_LEN, NHI_N * CI_N), 256>>>((const float*)p_cq, w_iuq, (float*)p_qi,
                                                    DC_N, DC_N, NHI_N * CI_N, NHI_N * CI_N, 0, 0, 0);
  iscore_kernel<<<S_LEN, 256>>>();
  topk_kernel<<<S_LEN, 512>>>();

  // q path (tensor tf32 — continuous), then LN + rope in-place
  tgemm_kernel<<<grid2(S_LEN, NH_N * C_DIM), 256>>>((const float*)p_cq, w_uq, (float*)p_qf,
                                                    DC_N, DC_N, NH_N * C_DIM, NH_N * C_DIM, 0, 0, 0);
  qln_rope_kernel<<<S_LEN, dim3(64, 16)>>>(qn_w, qn_b);

  // sparse attention over top-k compressed chunks
  attn_kernel<<<S_LEN, 256>>>(sink);

  // grouped o_down: ONE batched launch (z = group), tensor
  tgemm_kernel<<<dim3(DG_N / 128, S_LEN / 128, NG_N), 256>>>(
      (const float*)p_ao, o_down, (float*)p_gb,
      256, NH_N * C_DIM, DG_N, NG_N * DG_N,
      /*sA=*/256, /*sB=*/(long)256 * DG_N, /*sC=*/DG_N);

  // o_up (tensor)
  tgemm_kernel<<<grid2(S_LEN, D_DIM), 256>>>((const float*)p_gb, o_up, out,
                                             NG_N * DG_N, NG_N * DG_N, D_DIM, D_DIM, 0, 0, 0);
}

// round 7
// speedup vs baseline: 1.6047x; 1.6047x over previous
#include <cuda_runtime.h>
#include <cstdint>
#include <cstddef>

// ---------------- problem constants ----------------
#define S_LEN   4096
#define D_DIM   2048
#define C_DIM   64
#define M_CH    4
#define NC_CH   1024
#define TOPK_N  512
#define NH_N    16
#define DC_N    512
#define NHI_N   4
#define CI_N    64
#define NG_N    4
#define DG_N    512

#define NEG_INF (__int_as_float(0xff800000))

// ---------------- scratch (device globals; no allocation allowed) -------
__device__ float g_ca[S_LEN * C_DIM];
__device__ float g_cb[S_LEN * C_DIM];
__device__ float g_za[S_LEN * C_DIM];
__device__ float g_zb[S_LEN * C_DIM];
__device__ float g_kc[NC_CH * C_DIM];
__device__ float g_cq[S_LEN * DC_N];
__device__ float g_qi[S_LEN * NHI_N * CI_N];
__device__ float g_hw[S_LEN * NHI_N];
__device__ float g_ko[NC_CH * D_DIM];
__device__ float g_kp[NC_CH * CI_N];
__device__ float g_qf[S_LEN * NH_N * C_DIM];
__device__ float g_is[(size_t)S_LEN * NC_CH];
__device__ int   g_ti[S_LEN * TOPK_N];
__device__ float g_ao[S_LEN * NH_N * C_DIM];
__device__ float g_gb[(size_t)S_LEN * NG_N * DG_N];

// ---------------- tf32 helpers ----------------
__device__ __forceinline__ uint32_t f2tf(float v) {
  uint32_t h;
  asm("cvt.rna.tf32.f32 %0, %1;" : "=r"(h) : "f"(v));
  return h;
}

__device__ __forceinline__ void mma_tf32(float* c, const uint32_t* a, const uint32_t* b) {
  asm volatile(
      "mma.sync.aligned.m16n8k8.row.col.f32.tf32.tf32.f32 "
      "{%0,%1,%2,%3}, {%4,%5,%6,%7}, {%8,%9}, {%0,%1,%2,%3};"
      : "+f"(c[0]), "+f"(c[1]), "+f"(c[2]), "+f"(c[3])
      : "r"(a[0]), "r"(a[1]), "r"(a[2]), "r"(a[3]), "r"(b[0]), "r"(b[1]));
}

// ========== tensor GEMM, tf32 3x split, CONVERT-AT-STORE ================
// C = A(MxK) @ B(KxN). 128x128 tile, BK=16, 256 threads (8 warps 2x4),
// per-warp 64x32. Smem holds pre-split tf32 hi/lo planes; inner loop is
// pure LDS + HMMA. Batched via blockIdx.z strides.
__global__ __launch_bounds__(256) void tgemm_kernel(
    const float* __restrict__ A, const float* __restrict__ B,
    float* __restrict__ Cc, int K, int lda, int ldb, int ldc,
    long sA, long sB, long sC) {
  A += (long)blockIdx.z * sA;
  B += (long)blockIdx.z * sB;
  Cc += (long)blockIdx.z * sC;

  // A planes: [row][k], stride 20 -> fragment banks (20g+t) conflict-free
  // B planes: [k][col], stride 136 -> fragment banks (8t+g) conflict-free
  __shared__ uint32_t Ah[128][20], Al[128][20];
  __shared__ uint32_t Bh[16][136], Bl[16][136];

  const int bm = blockIdx.y * 128;
  const int bn = blockIdx.x * 128;
  const int tid = threadIdx.x;
  const int warp = tid >> 5, lane = tid & 31;
  const int wm = warp >> 2, wn = warp & 3;  // 2 x 4 warp grid
  const int g = lane >> 2, t = lane & 3;

  const int arow = tid >> 1, akoff = (tid & 1) * 8;
  const int brow = tid >> 5, bcol = lane * 4;

  const float* Aptr = A + (size_t)(bm + arow) * lda + akoff;
  const float* Bptr = B + (size_t)brow * ldb + bn + bcol;

  float acc[4][4][4];
#pragma unroll
  for (int i = 0; i < 4; i++)
#pragma unroll
    for (int j = 0; j < 4; j++)
#pragma unroll
      for (int r = 0; r < 4; r++) acc[i][j][r] = 0.f;

  // preload slab 0 into registers
  float4 av0 = *reinterpret_cast<const float4*>(Aptr);
  float4 av1 = *reinterpret_cast<const float4*>(Aptr + 4);
  float4 bv0 = *reinterpret_cast<const float4*>(Bptr);
  float4 bv1 = *reinterpret_cast<const float4*>(Bptr + (size_t)8 * ldb);

  for (int k0 = 0; k0 < K; k0 += 16) {
    // convert current slab regs -> smem hi/lo planes (uint4 stores)
    {
      float af[8] = {av0.x, av0.y, av0.z, av0.w, av1.x, av1.y, av1.z, av1.w};
      uint32_t h[8], l[8];
#pragma unroll
      for (int i = 0; i < 8; i++) {
        h[i] = f2tf(af[i]);
        l[i] = f2tf(af[i] - __uint_as_float(h[i]));
      }
      *reinterpret_cast<uint4*>(&Ah[arow][akoff]) = make_uint4(h[0], h[1], h[2], h[3]);
      *reinterpret_cast<uint4*>(&Ah[arow][akoff + 4]) = make_uint4(h[4], h[5], h[6], h[7]);
      *reinterpret_cast<uint4*>(&Al[arow][akoff]) = make_uint4(l[0], l[1], l[2], l[3]);
      *reinterpret_cast<uint4*>(&Al[arow][akoff + 4]) = make_uint4(l[4], l[5], l[6], l[7]);

      float bf0[4] = {bv0.x, bv0.y, bv0.z, bv0.w};
      float bf1[4] = {bv1.x, bv1.y, bv1.z, bv1.w};
      uint32_t bh0[4], bl0[4], bh1[4], bl1[4];
#pragma unroll
      for (int i = 0; i < 4; i++) {
        bh0[i] = f2tf(bf0[i]);
        bl0[i] = f2tf(bf0[i] - __uint_as_float(bh0[i]));
        bh1[i] = f2tf(bf1[i]);
        bl1[i] = f2tf(bf1[i] - __uint_as_float(bh1[i]));
      }
      *reinterpret_cast<uint4*>(&Bh[brow][bcol]) = make_uint4(bh0[0], bh0[1], bh0[2], bh0[3]);
      *reinterpret_cast<uint4*>(&Bl[brow][bcol]) = make_uint4(bl0[0], bl0[1], bl0[2], bl0[3]);
      *reinterpret_cast<uint4*>(&Bh[brow + 8][bcol]) = make_uint4(bh1[0], bh1[1], bh1[2], bh1[3]);
      *reinterpret_cast<uint4*>(&Bl[brow + 8][bcol]) = make_uint4(bl1[0], bl1[1], bl1[2], bl1[3]);
    }
    __syncthreads();

    // prefetch next slab (overlaps with compute below)
    const bool more = (k0 + 16 < K);
    if (more) {
      av0 = *reinterpret_cast<const float4*>(Aptr + k0 + 16);
      av1 = *reinterpret_cast<const float4*>(Aptr + k0 + 20);
      bv0 = *reinterpret_cast<const float4*>(Bptr + (size_t)(k0 + 16) * ldb);
      bv1 = *reinterpret_cast<const float4*>(Bptr + (size_t)(k0 + 24) * ldb);
    }

    // compute: pure LDS + HMMA
#pragma unroll
    for (int ks = 0; ks < 16; ks += 8) {
      uint32_t bhf[4][2], blf[4][2];
#pragma unroll
      for (int ni = 0; ni < 4; ni++) {
        int colB = wn * 32 + ni * 8 + g;
        bhf[ni][0] = Bh[ks + t][colB];
        bhf[ni][1] = Bh[ks + t + 4][colB];
        blf[ni][0] = Bl[ks + t][colB];
        blf[ni][1] = Bl[ks + t + 4][colB];
      }
#pragma unroll
      for (int mi = 0; mi < 4; mi++) {
        int rowA = wm * 64 + mi * 16 + g;
        uint32_t ah[4], al[4];
        ah[0] = Ah[rowA][ks + t];
        ah[1] = Ah[rowA + 8][ks + t];
        ah[2] = Ah[rowA][ks + t + 4];
        ah[3] = Ah[rowA + 8][ks + t + 4];
        al[0] = Al[rowA][ks + t];
        al[1] = Al[rowA + 8][ks + t];
        al[2] = Al[rowA][ks + t + 4];
        al[3] = Al[rowA + 8][ks + t + 4];
        // interleave terms across independent ni accumulators
#pragma unroll
        for (int ni = 0; ni < 4; ni++) mma_tf32(acc[mi][ni], ah, bhf[ni]);
#pragma unroll
        for (int ni = 0; ni < 4; ni++) mma_tf32(acc[mi][ni], ah, blf[ni]);
#pragma unroll
        for (int ni = 0; ni < 4; ni++) mma_tf32(acc[mi][ni], al, bhf[ni]);
      }
    }
    __syncthreads();  // before overwriting smem next slab
  }

  // epilogue (mapping verified by R6 pass)
#pragma unroll
  for (int mi = 0; mi < 4; mi++) {
    int row0 = bm + wm * 64 + mi * 16 + g;
#pragma unroll
    for (int ni = 0; ni < 4; ni++) {
      int col = bn + wn * 32 + ni * 8 + 2 * t;
      *reinterpret_cast<float2*>(Cc + (size_t)row0 * ldc + col) =
          make_float2(acc[mi][ni][0], acc[mi][ni][1]);
      *reinterpret_cast<float2*>(Cc + (size_t)(row0 + 8) * ldc + col) =
          make_float2(acc[mi][ni][2], acc[mi][ni][3]);
    }
  }
}

// ========== fp32 SGEMM (R4-exact) — DISCRETE-feeding path (c_q, q_i) ====
__global__ __launch_bounds__(256, 2) void sgemm_kernel(
    const float* __restrict__ A, const float* __restrict__ B,
    float* __restrict__ Cc, int K, int lda, int ldb, int ldc,
    long sA, long sB, long sC) {
  A += (long)blockIdx.z * sA;
  B += (long)blockIdx.z * sB;
  Cc += (long)blockIdx.z * sC;

  __shared__ float As[2][8][128];
  __shared__ float Bs[2][8][132];
  const int bm = blockIdx.y * 128;
  const int bn = blockIdx.x * 128;
  const int tid = threadIdx.x;
  const int tx = tid & 15, ty = tid >> 4;
  const int arow = tid >> 1, acol = (tid & 1) * 4;
  const int brow = tid >> 5, bcol = (tid & 31) * 4;

  const float* Aptr = A + (size_t)(bm + arow) * lda + acol;
  const float* Bptr = B + (size_t)brow * ldb + bn + bcol;

  float acc[8][8];
#pragma unroll
  for (int i = 0; i < 8; i++)
#pragma unroll
    for (int j = 0; j < 8; j++) acc[i][j] = 0.f;

  {
    float4 av = *reinterpret_cast<const float4*>(Aptr);
    float4 bv = *reinterpret_cast<const float4*>(Bptr);
    As[0][acol + 0][arow] = av.x;
    As[0][acol + 1][arow] = av.y;
    As[0][acol + 2][arow] = av.z;
    As[0][acol + 3][arow] = av.w;
    Bs[0][brow][bcol + 0] = bv.x;
    Bs[0][brow][bcol + 1] = bv.y;
    Bs[0][brow][bcol + 2] = bv.z;
    Bs[0][brow][bcol + 3] = bv.w;
  }
  __syncthreads();

  int buf = 0;
  for (int k0 = 0; k0 < K; k0 += 8) {
    float4 av, bv;
    const bool more = (k0 + 8 < K);
    if (more) {
      av = *reinterpret_cast<const float4*>(Aptr + k0 + 8);
      bv = *reinterpret_cast<const float4*>(Bptr + (size_t)(k0 + 8) * ldb);
    }
#pragma unroll
    for (int kk = 0; kk < 8; kk++) {
      float a[8], b[8];
#pragma unroll
      for (int i = 0; i < 8; i++) a[i] = As[buf][kk][ty * 8 + i];
#pragma unroll
      for (int j = 0; j < 8; j++) b[j] = Bs[buf][kk][tx * 8 + j];
#pragma unroll
      for (int i = 0; i < 8; i++)
#pragma unroll
        for (int j = 0; j < 8; j++) acc[i][j] += a[i] * b[j];
    }
    if (more) {
      int nb = buf ^ 1;
      As[nb][acol + 0][arow] = av.x;
      As[nb][acol + 1][arow] = av.y;
      As[nb][acol + 2][arow] = av.z;
      As[nb][acol + 3][arow] = av.w;
      Bs[nb][brow][bcol + 0] = bv.x;
      Bs[nb][brow][bcol + 1] = bv.y;
      Bs[nb][brow][bcol + 2] = bv.z;
      Bs[nb][brow][bcol + 3] = bv.w;
      __syncthreads();
      buf = nb;
    }
  }

#pragma unroll
  for (int i = 0; i < 8; i++) {
    float* crow = Cc + (size_t)(bm + ty * 8 + i) * ldc + bn + tx * 8;
    *reinterpret_cast<float4*>(crow) = make_float4(acc[i][0], acc[i][1], acc[i][2], acc[i][3]);
    *reinterpret_cast<float4*>(crow + 4) = make_float4(acc[i][4], acc[i][5], acc[i][6], acc[i][7]);
  }
}

// ========== fused narrow projections: 5 independent (A @ B[2048x64]) ====
struct ProjArgs {
  const float* A[5];
  const float* B[5];
  float* Cc[5];
  int M[5];
};

__global__ __launch_bounds__(256, 2) void proj64_kernel(ProjArgs pa) {
  const int mat = blockIdx.x;
  const int bm = blockIdx.y * 128;
  if (bm >= pa.M[mat]) return;
  const float* A = pa.A[mat];
  const float* B = pa.B[mat];
  float* Cc = pa.Cc[mat];

  __shared__ float As[8][128];
  __shared__ float Bs[8][68];
  const int tid = threadIdx.x;
  const int tx = tid & 15, ty = tid >> 4;
  const int arow = tid >> 1, acol = (tid & 1) * 4;
  const int brow = tid >> 4, bcol = (tid & 15) * 4;
  const bool bload = (tid < 128);

  const float* Aptr = A + (size_t)(bm + arow) * D_DIM + acol;
  const float* Bptr = B + (size_t)brow * C_DIM + bcol;

  float acc[8][4];
#pragma unroll
  for (int i = 0; i < 8; i++)
#pragma unroll
    for (int j = 0; j < 4; j++) acc[i][j] = 0.f;

  float4 av = *reinterpret_cast<const float4*>(Aptr);
  float4 bv = bload ? *reinterpret_cast<const float4*>(Bptr) : make_float4(0, 0, 0, 0);

  for (int k0 = 0; k0 < D_DIM; k0 += 8) {
    As[acol + 0][arow] = av.x;
    As[acol + 1][arow] = av.y;
    As[acol + 2][arow] = av.z;
    As[acol + 3][arow] = av.w;
    if (bload) {
      Bs[brow][bcol + 0] = bv.x;
      Bs[brow][bcol + 1] = bv.y;
      Bs[brow][bcol + 2] = bv.z;
      Bs[brow][bcol + 3] = bv.w;
    }
    __syncthreads();

    if (k0 + 8 < D_DIM) {
      av = *reinterpret_cast<const float4*>(Aptr + k0 + 8);
      if (bload) bv = *reinterpret_cast<const float4*>(Bptr + (size_t)(k0 + 8) * C_DIM);
    }

#pragma unroll
    for (int kk = 0; kk < 8; kk++) {
      float a[8], b[4];
#pragma unroll
      for (int i = 0; i < 8; i++) a[i] = As[kk][ty * 8 + i];
#pragma unroll
      for (int j = 0; j < 4; j++) b[j] = Bs[kk][tx * 4 + j];
#pragma unroll
      for (int i = 0; i < 8; i++)
#pragma unroll
        for (int j = 0; j < 4; j++) acc[i][j] += a[i] * b[j];
    }
    __syncthreads();
  }

#pragma unroll
  for (int i = 0; i < 8; i++) {
    float* crow = Cc + (size_t)(bm + ty * 8 + i) * C_DIM + tx * 4;
    *reinterpret_cast<float4*>(crow) = make_float4(acc[i][0], acc[i][1], acc[i][2], acc[i][3]);
  }
}

// ========== hw = x @ w_w [2048x4]: one warp per row ====================
__global__ void hw_kernel(const float* __restrict__ x, const float* __restrict__ w_w) {
  int warp = (blockIdx.x * blockDim.x + threadIdx.x) >> 5;
  int lane = threadIdx.x & 31;
  if (warp >= S_LEN) return;
  const float4* xr = reinterpret_cast<const float4*>(x + (size_t)warp * D_DIM);
  const float4* wr = reinterpret_cast<const float4*>(w_w);
  float d0 = 0.f, d1 = 0.f, d2 = 0.f, d3 = 0.f;
  for (int i = lane; i < D_DIM / 4; i += 32) {
    float4 xv = xr[i];
    float4 w0 = wr[i * 4 + 0];
    float4 w1 = wr[i * 4 + 1];
    float4 w2 = wr[i * 4 + 2];
    float4 w3 = wr[i * 4 + 3];
    d0 += xv.x * w0.x + xv.y * w1.x + xv.z * w2.x + xv.w * w3.x;
    d1 += xv.x * w0.y + xv.y * w1.y + xv.z * w2.y + xv.w * w3.y;
    d2 += xv.x * w0.z + xv.y * w1.z + xv.z * w2.z + xv.w * w3.z;
    d3 += xv.x * w0.w + xv.y * w1.w + xv.z * w2.w + xv.w * w3.w;
  }
#pragma unroll
  for (int off = 16; off > 0; off >>= 1) {
    d0 += __shfl_down_sync(0xffffffffu, d0, off);
    d1 += __shfl_down_sync(0xffffffffu, d1, off);
    d2 += __shfl_down_sync(0xffffffffu, d2, off);
    d3 += __shfl_down_sync(0xffffffffu, d3, off);
  }
  if (lane == 0) {
    g_hw[warp * 4 + 0] = d0;
    g_hw[warp * 4 + 1] = d1;
    g_hw[warp * 4 + 2] = d2;
    g_hw[warp * 4 + 3] = d3;
  }
}

// ---------------- k_orig = mean over the M=4 tokens of each chunk -------
__global__ void kmean_kernel(const float* __restrict__ x) {
  int idx = blockIdx.x * 256 + threadIdx.x;
  if (idx >= NC_CH * D_DIM) return;
  int nc = idx / D_DIM, d = idx - nc * D_DIM;
  const float* p = x + (size_t)nc * 4 * D_DIM + d;
  g_ko[idx] = 0.25f * (p[0] + p[D_DIM] + p[2 * D_DIM] + p[3 * D_DIM]);
}

// ------------- compression softmax (over 8 candidates) + LayerNorm ------
__global__ void compress_kernel(const float* __restrict__ b_a,
                                const float* __restrict__ b_b,
                                const float* __restrict__ kvn_w,
                                const float* __restrict__ kvn_b) {
  int nc = blockIdx.x;
  int c = threadIdx.x;  // 64
  float lg[8], val[8];
#pragma unroll
  for (int m = 0; m < 4; m++) {
    int cur = (nc * 4 + m) * 64 + c;
    lg[4 + m] = g_za[cur] + b_a[m * 64 + c];
    val[4 + m] = g_ca[cur];
    if (nc > 0) {
      int prev = ((nc - 1) * 4 + m) * 64 + c;
      lg[m] = g_zb[prev] + b_b[m * 64 + c];
      val[m] = g_cb[prev];
    } else {
      lg[m] = -1e30f + b_b[m * 64 + c];
      val[m] = 0.f;
    }
  }
  float mx = lg[0];
#pragma unroll
  for (int i = 1; i < 8; i++) mx = fmaxf(mx, lg[i]);
  float se = 0.f, comp = 0.f;
#pragma unroll
  for (int i = 0; i < 8; i++) {
    float e = expf(lg[i] - mx);
    se += e;
    comp += e * val[i];
  }
  comp /= se;

  __shared__ float red[64];
  red[c] = comp;
  __syncthreads();
  for (int off = 32; off > 0; off >>= 1) {
    if (c < off) red[c] += red[c + off];
    __syncthreads();
  }
  float mu = red[0] * (1.f / 64.f);
  __syncthreads();
  float dv = comp - mu;
  red[c] = dv * dv;
  __syncthreads();
  for (int off = 32; off > 0; off >>= 1) {
    if (c < off) red[c] += red[c + off];
    __syncthreads();
  }
  float var = red[0] * (1.f / 64.f);
  g_kc[nc * 64 + c] = dv * rsqrtf(var + 1e-6f) * kvn_w[c] + kvn_b[c];
}

// ------------- per-(s,h) LayerNorm then RoPE on last 32 channels --------
__global__ void qln_rope_kernel(const float* __restrict__ qn_w,
                                const float* __restrict__ qn_b) {
  int s = blockIdx.x;
  int c = threadIdx.x;  // 64
  int h = threadIdx.y;  // 16
  float v = g_qf[(size_t)s * 1024 + h * 64 + c];
  __shared__ float red[16][64];
  __shared__ float lnb[16][65];
  red[h][c] = v;
  __syncthreads();
  for (int off = 32; off > 0; off >>= 1) {
    if (c < off) red[h][c] += red[h][c + off];
    __syncthreads();
  }
  float mu = red[h][0] * (1.f / 64.f);
  __syncthreads();
  float dv = v - mu;
  red[h][c] = dv * dv;
  __syncthreads();
  for (int off = 32; off > 0; off >>= 1) {
    if (c < off) red[h][c] += red[h][c + off];
    __syncthreads();
  }
  float var = red[h][0] * (1.f / 64.f);
  float ln = dv * rsqrtf(var + 1e-6f) * qn_w[c] + qn_b[c];
  lnb[h][c] = ln;
  __syncthreads();
  float outv;
  if (c < 32) {
    outv = ln;
  } else {
    int j = (c - 32) >> 1;
    float inv = exp2f(-(float)j * 0.830482023722f);  // 10000^(-j/16)
    float ang = (float)s * inv;
    float cs = cosf(ang), sn = sinf(ang);
    float x0 = lnb[h][32 + 2 * j], x1 = lnb[h][32 + 2 * j + 1];
    outv = ((c & 1) == 0) ? (x0 * cs - x1 * sn) : (x0 * sn + x1 * cs);
  }
  g_qf[(size_t)s * 1024 + h * 64 + c] = outv;
}

// ------------- indexer scores: relu(q_i . k_proj) weighted by hw --------
__global__ void iscore_kernel() {
  int s = blockIdx.x;
  __shared__ float qs[256];
  __shared__ float ws[4];
  int tid = threadIdx.x;  // 256
  qs[tid] = g_qi[(size_t)s * 256 + tid];
  if (tid < 4) ws[tid] = g_hw[s * 4 + tid];
  __syncthreads();
  const float4* qs4 = reinterpret_cast<const float4*>(qs);
  for (int k = tid; k < NC_CH; k += 256) {
    const float4* kr = reinterpret_cast<const float4*>(g_kp + k * 64);
    float d0 = 0.f, d1 = 0.f, d2 = 0.f, d3 = 0.f;
#pragma unroll
    for (int c4 = 0; c4 < 16; c4++) {
      float4 kv = kr[c4];
      float4 q0 = qs4[c4];
      float4 q1 = qs4[16 + c4];
      float4 q2 = qs4[32 + c4];
      float4 q3 = qs4[48 + c4];
      d0 += q0.x * kv.x + q0.y * kv.y + q0.z * kv.z + q0.w * kv.w;
      d1 += q1.x * kv.x + q1.y * kv.y + q1.z * kv.z + q1.w * kv.w;
      d2 += q2.x * kv.x + q2.y * kv.y + q2.z * kv.z + q2.w * kv.w;
      d3 += q3.x * kv.x + q3.y * kv.y + q3.z * kv.z + q3.w * kv.w;
    }
    float sc = fmaxf(d0, 0.f) * ws[0] + fmaxf(d1, 0.f) * ws[1] +
               fmaxf(d2, 0.f) * ws[2] + fmaxf(d3, 0.f) * ws[3];
    g_is[(size_t)s * NC_CH + k] = (k < s) ? sc : NEG_INF;
  }
}

// ------------- exact top-512: bitonic sort by (value desc, index asc) ---
__global__ __launch_bounds__(512) void topk_kernel() {
  int s = blockIdx.x, tid = threadIdx.x;  // 512
  __shared__ float v[1024];
  __shared__ int ix[1024];
  v[tid] = g_is[(size_t)s * 1024 + tid];
  ix[tid] = tid;
  v[tid + 512] = g_is[(size_t)s * 1024 + tid + 512];
  ix[tid + 512] = tid + 512;
  __syncthreads();
  for (int k = 2; k <= 1024; k <<= 1) {
    for (int j = k >> 1; j > 0; j >>= 1) {
      for (int t = tid; t < 1024; t += 512) {
        int p = t ^ j;
        if (p > t) {
          float va = v[t], vb = v[p];
          int ia = ix[t], ib = ix[p];
          bool before = (va > vb) || (va == vb && ia < ib);
          bool dir = ((t & k) == 0);
          if (before != dir) {
            v[t] = vb; v[p] = va;
            ix[t] = ib; ix[p] = ia;
          }
        }
      }
      __syncthreads();
    }
  }
  g_ti[(size_t)s * 512 + tid] = ix[tid];
}

// ------------- gathered sparse attention (4 quarters of 128 chunks) -----
__global__ __launch_bounds__(256) void attn_kernel(const float* __restrict__ sink) {
  const int s = blockIdx.x, tid = threadIdx.x;  // 256
  __shared__ float qs[1024];
  __shared__ float Ks[128][68];
  __shared__ float ew[16][128];
  __shared__ float denom[16];

#pragma unroll
  for (int i = 0; i < 4; i++) qs[tid + 256 * i] = g_qf[(size_t)s * 1024 + tid + 256 * i];
  if (tid < 16) denom[tid] = __expf(sink[tid]);
  __syncthreads();

  const int c = tid & 63, g = tid >> 6;
  float acc0 = 0.f, acc1 = 0.f, acc2 = 0.f, acc3 = 0.f;
  const float4* qs4 = reinterpret_cast<const float4*>(qs);
  const int* trow = g_ti + (size_t)s * 512;

  for (int qtr = 0; qtr < 4; qtr++) {
    if (qtr) __syncthreads();

    {
      int j = tid >> 1, p = tid & 1;
      int ck = trow[qtr * 128 + j];
      const float4* src = reinterpret_cast<const float4*>(g_kc + ck * 64);
      float4* dst = reinterpret_cast<float4*>(&Ks[j][0]);
#pragma unroll
      for (int q = 0; q < 8; q++) dst[p + 2 * q] = src[p + 2 * q];
    }
    __syncthreads();

    {
      int kk = tid >> 1, hh = (tid & 1) * 8;
      int ck = trow[qtr * 128 + kk];
      bool valid = (s < ck * 4);
      const float4* kr = reinterpret_cast<const float4*>(&Ks[kk][0]);
      float d[8];
#pragma unroll
      for (int h = 0; h < 8; h++) d[h] = 0.f;
#pragma unroll
      for (int c4 = 0; c4 < 16; c4++) {
        float4 kv = kr[c4];
#pragma unroll
        for (int h = 0; h < 8; h++) {
          float4 qv = qs4[(hh + h) * 16 + c4];
          d[h] += qv.x * kv.x + qv.y * kv.y + qv.z * kv.z + qv.w * kv.w;
        }
      }
#pragma unroll
      for (int h = 0; h < 8; h++) ew[hh + h][kk] = valid ? __expf(d[h] * 0.125f) : 0.f;
    }
    __syncthreads();

    {
      int h = tid >> 4, seg = tid & 15;
      float p = 0.f;
#pragma unroll
      for (int k = 0; k < 8; k++) p += ew[h][seg * 8 + k];
#pragma unroll
      for (int off = 8; off > 0; off >>= 1) p += __shfl_down_sync(0xffffffffu, p, off);
      if (seg == 0) denom[h] += p;
    }

    for (int k = 0; k < 128; k++) {
      float kv = Ks[k][c];
      acc0 += ew[g][k] * kv;
      acc1 += ew[g + 4][k] * kv;
      acc2 += ew[g + 8][k] * kv;
      acc3 += ew[g + 12][k] * kv;
    }
  }
  __syncthreads();

  g_ao[(size_t)s * 1024 + (g) * 64 + c] = acc0 / denom[g];
  g_ao[(size_t)s * 1024 + (g + 4) * 64 + c] = acc1 / denom[g + 4];
  g_ao[(size_t)s * 1024 + (g + 8) * 64 + c] = acc2 / denom[g + 8];
  g_ao[(size_t)s * 1024 + (g + 12) * 64 + c] = acc3 / denom[g + 12];
}

// ---------------------------- launcher ----------------------------------
extern "C" void kernel_launch(void* const* d_in, const int* in_sizes, int n_in,
                              void* d_out, int out_size) {
  (void)in_sizes; (void)n_in; (void)out_size;
  const float* x      = (const float*)d_in[0];
  const float* w_kva  = (const float*)d_in[1];
  const float* w_kvb  = (const float*)d_in[2];
  const float* w_za   = (const float*)d_in[3];
  const float* w_zb   = (const float*)d_in[4];
  const float* b_a    = (const float*)d_in[5];
  const float* b_b    = (const float*)d_in[6];
  const float* w_dq   = (const float*)d_in[7];
  const float* w_iuq  = (const float*)d_in[8];
  const float* w_w    = (const float*)d_in[9];
  const float* w_k    = (const float*)d_in[10];
  const float* w_uq   = (const float*)d_in[11];
  const float* o_down = (const float*)d_in[12];
  const float* o_up   = (const float*)d_in[13];
  const float* kvn_w  = (const float*)d_in[14];
  const float* kvn_b  = (const float*)d_in[15];
  const float* qn_w   = (const float*)d_in[16];
  const float* qn_b   = (const float*)d_in[17];
  const float* sink   = (const float*)d_in[18];
  float* out = (float*)d_out;

  void *p_ca, *p_cb, *p_za, *p_zb, *p_cq, *p_qi, *p_ko, *p_kp, *p_qf, *p_ao, *p_gb;
  cudaGetSymbolAddress(&p_ca, g_ca);
  cudaGetSymbolAddress(&p_cb, g_cb);
  cudaGetSymbolAddress(&p_za, g_za);
  cudaGetSymbolAddress(&p_zb, g_zb);
  cudaGetSymbolAddress(&p_cq, g_cq);
  cudaGetSymbolAddress(&p_qi, g_qi);
  cudaGetSymbolAddress(&p_ko, g_ko);
  cudaGetSymbolAddress(&p_kp, g_kp);
  cudaGetSymbolAddress(&p_qf, g_qf);
  cudaGetSymbolAddress(&p_ao, g_ao);
  cudaGetSymbolAddress(&p_gb, g_gb);

  auto grid2 = [](int M, int N) { return dim3((unsigned)(N / 128), (unsigned)(M / 128), 1u); };

  // chunk means first (feeds k_proj inside fused projections)
  kmean_kernel<<<(NC_CH * D_DIM + 255) / 256, 256>>>(x);

  // fused narrow projections
  ProjArgs pa;
  pa.A[0] = x;     pa.B[0] = w_kva; pa.Cc[0] = (float*)p_ca; pa.M[0] = S_LEN;
  pa.A[1] = x;     pa.B[1] = w_kvb; pa.Cc[1] = (float*)p_cb; pa.M[1] = S_LEN;
  pa.A[2] = x;     pa.B[2] = w_za;  pa.Cc[2] = (float*)p_za; pa.M[2] = S_LEN;
  pa.A[3] = x;     pa.B[3] = w_zb;  pa.Cc[3] = (float*)p_zb; pa.M[3] = S_LEN;
  pa.A[4] = (const float*)p_ko; pa.B[4] = w_k; pa.Cc[4] = (float*)p_kp; pa.M[4] = NC_CH;
  proj64_kernel<<<dim3(5, S_LEN / 128), 256>>>(pa);

  // hw = x @ w_w
  hw_kernel<<<S_LEN / 8, 256>>>(x, w_w);

  // c_q = x @ w_dq  (fp32 — feeds the discrete top-k path)
  sgemm_kernel<<<grid2(S_LEN, DC_N), 256>>>(x, w_dq, (float*)p_cq, D_DIM, D_DIM, DC_N, DC_N, 0, 0, 0);

  // chunk compression + LN(kc)
  compress_kernel<<<NC_CH, 64>>>(b_a, b_b, kvn_w, kvn_b);

  // indexer path (fp32 — discrete)
  sgemm_kernel<<<grid2(S_LEN, NHI_N * CI_N), 256>>>((const float*)p_cq, w_iuq, (float*)p_qi,
                                                    DC_N, DC_N, NHI_N * CI_N, NHI_N * CI_N, 0, 0, 0);
  iscore_kernel<<<S_LEN, 256>>>();
  topk_kernel<<<S_LEN, 512>>>();

  // q path (tensor tf32 3x — continuous), then LN + rope in-place
  tgemm_kernel<<<grid2(S_LEN, NH_N * C_DIM), 256>>>((const float*)p_cq, w_uq, (float*)p_qf,
                                                    DC_N, DC_N, NH_N * C_DIM, NH_N * C_DIM, 0, 0, 0);
  qln_rope_kernel<<<S_LEN, dim3(64, 16)>>>(qn_w, qn_b);

  // sparse attention over top-k compressed chunks
  attn_kernel<<<S_LEN, 256>>>(sink);

  // grouped o_down: ONE batched launch (z = group), tensor
  tgemm_kernel<<<dim3(DG_N / 128, S_LEN / 128, NG_N), 256>>>(
      (const float*)p_ao, o_down, (float*)p_gb,
      256, NH_N * C_DIM, DG_N, NG_N * DG_N,
      /*sA=*/256, /*sB=*/(long)256 * DG_N, /*sC=*/DG_N);

  // o_up (tensor)
  tgemm_kernel<<<grid2(S_LEN, D_DIM), 256>>>((const float*)p_gb, o_up, out,
                                             NG_N * DG_N, NG_N * DG_N, D_DIM, D_DIM, 0, 0, 0);
}

// round 8
// speedup vs baseline: 1.9096x; 1.1900x over previous
#include <cuda_runtime.h>
#include <cuda_bf16.h>
#include <cstdint>
#include <cstddef>

// ---------------- problem constants ----------------
#define S_LEN   4096
#define D_DIM   2048
#define C_DIM   64
#define M_CH    4
#define NC_CH   1024
#define TOPK_N  512
#define NH_N    16
#define DC_N    512
#define NHI_N   4
#define CI_N    64
#define NG_N    4
#define DG_N    512

#define NEG_INF (__int_as_float(0xff800000))

// ---------------- scratch (device globals; no allocation allowed) -------
__device__ float g_ca[S_LEN * C_DIM];
__device__ float g_cb[S_LEN * C_DIM];
__device__ float g_za[S_LEN * C_DIM];
__device__ float g_zb[S_LEN * C_DIM];
__device__ float g_kc[NC_CH * C_DIM];
__device__ float g_cq[S_LEN * DC_N];
__device__ float g_qi[S_LEN * NHI_N * CI_N];
__device__ float g_hw[S_LEN * NHI_N];
__device__ float g_ko[NC_CH * D_DIM];
__device__ float g_kp[NC_CH * CI_N];
__device__ float g_qf[S_LEN * NH_N * C_DIM];
__device__ float g_is[(size_t)S_LEN * NC_CH];
__device__ int   g_ti[S_LEN * TOPK_N];
__device__ float g_ao[S_LEN * NH_N * C_DIM];
__device__ float g_gb[(size_t)S_LEN * NG_N * DG_N];

// ---------------- bf16 helpers ----------------
// pack two floats into bf16x2: bits[15:0] = bf16(e0) (element k), bits[31:16] = bf16(e1) (k+1)
__device__ __forceinline__ uint32_t pack_bf16(float e0, float e1) {
  uint32_t d;
  asm("cvt.rn.bf16x2.f32 %0, %1, %2;" : "=r"(d) : "f"(e1), "f"(e0));
  return d;
}

// split pair (a0 at k, a1 at k+1) into hi/lo bf16x2 planes
__device__ __forceinline__ void split_pair(float a0, float a1, uint32_t& hp, uint32_t& lp) {
  hp = pack_bf16(a0, a1);
  float r0 = a0 - __uint_as_float(hp << 16);
  float r1 = a1 - __uint_as_float(hp & 0xffff0000u);
  lp = pack_bf16(r0, r1);
}

__device__ __forceinline__ void mma_bf16(float* c, const uint32_t* a, const uint32_t* b) {
  asm volatile(
      "mma.sync.aligned.m16n8k16.row.col.f32.bf16.bf16.f32 "
      "{%0,%1,%2,%3}, {%4,%5,%6,%7}, {%8,%9}, {%0,%1,%2,%3};"
      : "+f"(c[0]), "+f"(c[1]), "+f"(c[2]), "+f"(c[3])
      : "r"(a[0]), "r"(a[1]), "r"(a[2]), "r"(a[3]), "r"(b[0]), "r"(b[1]));
}

// ========== tensor GEMM, bf16 3-term split, convert-at-store ============
// C = A(MxK) @ B(KxN). 128x128 tile, BK=16, 256 threads (8 warps 2x4),
// per-warp 64x32 via m16n8k16. Smem holds packed bf16x2 hi/lo planes.
// Continuous-path only (w_uq / o_down / o_up). Batched via blockIdx.z.
__global__ __launch_bounds__(256) void tgemm_kernel(
    const float* __restrict__ A, const float* __restrict__ B,
    float* __restrict__ Cc, int K, int lda, int ldb, int ldc,
    long sA, long sB, long sC) {
  A += (long)blockIdx.z * sA;
  B += (long)blockIdx.z * sB;
  Cc += (long)blockIdx.z * sC;

  // A planes: [row][k/2] packed pairs, stride 12 (uint4-aligned, banks 12g+t distinct)
  // B planes: [k/2][col] packed pairs, stride 136 (banks 8t+g distinct)
  __shared__ uint32_t Ah[128][12], Al[128][12];
  __shared__ uint32_t Bh[8][136], Bl[8][136];

  const int bm = blockIdx.y * 128;
  const int bn = blockIdx.x * 128;
  const int tid = threadIdx.x;
  const int warp = tid >> 5, lane = tid & 31;
  const int wm = warp >> 2, wn = warp & 3;  // 2 x 4 warp grid
  const int g = lane >> 2, t = lane & 3;

  // A loader: thread -> row (tid>>1), k-half (tid&1)*8 (8 floats -> 4 pairs)
  const int arow = tid >> 1, akoff = (tid & 1) * 8;
  // B loader: thread r=tid>>5 handles B rows 2r,2r+1; cols lane*4..+3
  const int brp = tid >> 5, bcol = lane * 4;

  const float* Aptr = A + (size_t)(bm + arow) * lda + akoff;
  const float* Bptr0 = B + (size_t)(2 * brp) * ldb + bn + bcol;
  const float* Bptr1 = Bptr0 + ldb;

  float acc[4][4][4];
#pragma unroll
  for (int i = 0; i < 4; i++)
#pragma unroll
    for (int j = 0; j < 4; j++)
#pragma unroll
      for (int r = 0; r < 4; r++) acc[i][j][r] = 0.f;

  // preload slab 0 into registers
  float4 av0 = *reinterpret_cast<const float4*>(Aptr);
  float4 av1 = *reinterpret_cast<const float4*>(Aptr + 4);
  float4 bv0 = *reinterpret_cast<const float4*>(Bptr0);
  float4 bv1 = *reinterpret_cast<const float4*>(Bptr1);

  for (int k0 = 0; k0 < K; k0 += 16) {
    // convert current slab regs -> packed bf16x2 hi/lo planes
    {
      uint32_t h[4], l[4];
      split_pair(av0.x, av0.y, h[0], l[0]);
      split_pair(av0.z, av0.w, h[1], l[1]);
      split_pair(av1.x, av1.y, h[2], l[2]);
      split_pair(av1.z, av1.w, h[3], l[3]);
      int ac = akoff >> 1;  // 0 or 4
      *reinterpret_cast<uint4*>(&Ah[arow][ac]) = make_uint4(h[0], h[1], h[2], h[3]);
      *reinterpret_cast<uint4*>(&Al[arow][ac]) = make_uint4(l[0], l[1], l[2], l[3]);

      // B pairs along k: (row 2r, row 2r+1)
      uint32_t bh[4], bl[4];
      split_pair(bv0.x, bv1.x, bh[0], bl[0]);
      split_pair(bv0.y, bv1.y, bh[1], bl[1]);
      split_pair(bv0.z, bv1.z, bh[2], bl[2]);
      split_pair(bv0.w, bv1.w, bh[3], bl[3]);
      *reinterpret_cast<uint4*>(&Bh[brp][bcol]) = make_uint4(bh[0], bh[1], bh[2], bh[3]);
      *reinterpret_cast<uint4*>(&Bl[brp][bcol]) = make_uint4(bl[0], bl[1], bl[2], bl[3]);
    }
    __syncthreads();

    // prefetch next slab (overlaps compute)
    const bool more = (k0 + 16 < K);
    if (more) {
      av0 = *reinterpret_cast<const float4*>(Aptr + k0 + 16);
      av1 = *reinterpret_cast<const float4*>(Aptr + k0 + 20);
      bv0 = *reinterpret_cast<const float4*>(Bptr0 + (size_t)(k0 + 16) * ldb);
      bv1 = *reinterpret_cast<const float4*>(Bptr1 + (size_t)(k0 + 16) * ldb);
    }

    // compute: one m16n8k16 covers the whole 16-K slab per (term, mi, ni)
    {
      uint32_t bhf[4][2], blf[4][2];
#pragma unroll
      for (int ni = 0; ni < 4; ni++) {
        int colB = wn * 32 + ni * 8 + g;
        bhf[ni][0] = Bh[t][colB];      // k = 2t, 2t+1
        bhf[ni][1] = Bh[t + 4][colB];  // k = 8+2t, 8+2t+1
        blf[ni][0] = Bl[t][colB];
        blf[ni][1] = Bl[t + 4][colB];
      }
#pragma unroll
      for (int mi = 0; mi < 4; mi++) {
        int rowA = wm * 64 + mi * 16 + g;
        uint32_t ah[4], al[4];
        ah[0] = Ah[rowA][t];
        ah[1] = Ah[rowA + 8][t];
        ah[2] = Ah[rowA][t + 4];
        ah[3] = Ah[rowA + 8][t + 4];
        al[0] = Al[rowA][t];
        al[1] = Al[rowA + 8][t];
        al[2] = Al[rowA][t + 4];
        al[3] = Al[rowA + 8][t + 4];
#pragma unroll
        for (int ni = 0; ni < 4; ni++) mma_bf16(acc[mi][ni], ah, bhf[ni]);
#pragma unroll
        for (int ni = 0; ni < 4; ni++) mma_bf16(acc[mi][ni], ah, blf[ni]);
#pragma unroll
        for (int ni = 0; ni < 4; ni++) mma_bf16(acc[mi][ni], al, bhf[ni]);
      }
    }
    __syncthreads();  // before overwriting smem next slab
  }

  // epilogue (fragment mapping identical to verified tf32 version)
#pragma unroll
  for (int mi = 0; mi < 4; mi++) {
    int row0 = bm + wm * 64 + mi * 16 + g;
#pragma unroll
    for (int ni = 0; ni < 4; ni++) {
      int col = bn + wn * 32 + ni * 8 + 2 * t;
      *reinterpret_cast<float2*>(Cc + (size_t)row0 * ldc + col) =
          make_float2(acc[mi][ni][0], acc[mi][ni][1]);
      *reinterpret_cast<float2*>(Cc + (size_t)(row0 + 8) * ldc + col) =
          make_float2(acc[mi][ni][2], acc[mi][ni][3]);
    }
  }
}

// ========== fp32 SGEMM (R4-exact) — DISCRETE-feeding path (c_q, q_i) ====
__global__ __launch_bounds__(256, 2) void sgemm_kernel(
    const float* __restrict__ A, const float* __restrict__ B,
    float* __restrict__ Cc, int K, int lda, int ldb, int ldc,
    long sA, long sB, long sC) {
  A += (long)blockIdx.z * sA;
  B += (long)blockIdx.z * sB;
  Cc += (long)blockIdx.z * sC;

  __shared__ float As[2][8][128];
  __shared__ float Bs[2][8][132];
  const int bm = blockIdx.y * 128;
  const int bn = blockIdx.x * 128;
  const int tid = threadIdx.x;
  const int tx = tid & 15, ty = tid >> 4;
  const int arow = tid >> 1, acol = (tid & 1) * 4;
  const int brow = tid >> 5, bcol = (tid & 31) * 4;

  const float* Aptr = A + (size_t)(bm + arow) * lda + acol;
  const float* Bptr = B + (size_t)brow * ldb + bn + bcol;

  float acc[8][8];
#pragma unroll
  for (int i = 0; i < 8; i++)
#pragma unroll
    for (int j = 0; j < 8; j++) acc[i][j] = 0.f;

  {
    float4 av = *reinterpret_cast<const float4*>(Aptr);
    float4 bv = *reinterpret_cast<const float4*>(Bptr);
    As[0][acol + 0][arow] = av.x;
    As[0][acol + 1][arow] = av.y;
    As[0][acol + 2][arow] = av.z;
    As[0][acol + 3][arow] = av.w;
    Bs[0][brow][bcol + 0] = bv.x;
    Bs[0][brow][bcol + 1] = bv.y;
    Bs[0][brow][bcol + 2] = bv.z;
    Bs[0][brow][bcol + 3] = bv.w;
  }
  __syncthreads();

  int buf = 0;
  for (int k0 = 0; k0 < K; k0 += 8) {
    float4 av, bv;
    const bool more = (k0 + 8 < K);
    if (more) {
      av = *reinterpret_cast<const float4*>(Aptr + k0 + 8);
      bv = *reinterpret_cast<const float4*>(Bptr + (size_t)(k0 + 8) * ldb);
    }
#pragma unroll
    for (int kk = 0; kk < 8; kk++) {
      float a[8], b[8];
#pragma unroll
      for (int i = 0; i < 8; i++) a[i] = As[buf][kk][ty * 8 + i];
#pragma unroll
      for (int j = 0; j < 8; j++) b[j] = Bs[buf][kk][tx * 8 + j];
#pragma unroll
      for (int i = 0; i < 8; i++)
#pragma unroll
        for (int j = 0; j < 8; j++) acc[i][j] += a[i] * b[j];
    }
    if (more) {
      int nb = buf ^ 1;
      As[nb][acol + 0][arow] = av.x;
      As[nb][acol + 1][arow] = av.y;
      As[nb][acol + 2][arow] = av.z;
      As[nb][acol + 3][arow] = av.w;
      Bs[nb][brow][bcol + 0] = bv.x;
      Bs[nb][brow][bcol + 1] = bv.y;
      Bs[nb][brow][bcol + 2] = bv.z;
      Bs[nb][brow][bcol + 3] = bv.w;
      __syncthreads();
      buf = nb;
    }
  }

#pragma unroll
  for (int i = 0; i < 8; i++) {
    float* crow = Cc + (size_t)(bm + ty * 8 + i) * ldc + bn + tx * 8;
    *reinterpret_cast<float4*>(crow) = make_float4(acc[i][0], acc[i][1], acc[i][2], acc[i][3]);
    *reinterpret_cast<float4*>(crow + 4) = make_float4(acc[i][4], acc[i][5], acc[i][6], acc[i][7]);
  }
}

// ========== fused narrow projections: 5 independent (A @ B[2048x64]) ====
struct ProjArgs {
  const float* A[5];
  const float* B[5];
  float* Cc[5];
  int M[5];
};

__global__ __launch_bounds__(256, 2) void proj64_kernel(ProjArgs pa) {
  const int mat = blockIdx.x;
  const int bm = blockIdx.y * 128;
  if (bm >= pa.M[mat]) return;
  const float* A = pa.A[mat];
  const float* B = pa.B[mat];
  float* Cc = pa.Cc[mat];

  __shared__ float As[8][128];
  __shared__ float Bs[8][68];
  const int tid = threadIdx.x;
  const int tx = tid & 15, ty = tid >> 4;
  const int arow = tid >> 1, acol = (tid & 1) * 4;
  const int brow = tid >> 4, bcol = (tid & 15) * 4;
  const bool bload = (tid < 128);

  const float* Aptr = A + (size_t)(bm + arow) * D_DIM + acol;
  const float* Bptr = B + (size_t)brow * C_DIM + bcol;

  float acc[8][4];
#pragma unroll
  for (int i = 0; i < 8; i++)
#pragma unroll
    for (int j = 0; j < 4; j++) acc[i][j] = 0.f;

  float4 av = *reinterpret_cast<const float4*>(Aptr);
  float4 bv = bload ? *reinterpret_cast<const float4*>(Bptr) : make_float4(0, 0, 0, 0);

  for (int k0 = 0; k0 < D_DIM; k0 += 8) {
    As[acol + 0][arow] = av.x;
    As[acol + 1][arow] = av.y;
    As[acol + 2][arow] = av.z;
    As[acol + 3][arow] = av.w;
    if (bload) {
      Bs[brow][bcol + 0] = bv.x;
      Bs[brow][bcol + 1] = bv.y;
      Bs[brow][bcol + 2] = bv.z;
      Bs[brow][bcol + 3] = bv.w;
    }
    __syncthreads();

    if (k0 + 8 < D_DIM) {
      av = *reinterpret_cast<const float4*>(Aptr + k0 + 8);
      if (bload) bv = *reinterpret_cast<const float4*>(Bptr + (size_t)(k0 + 8) * C_DIM);
    }

#pragma unroll
    for (int kk = 0; kk < 8; kk++) {
      float a[8], b[4];
#pragma unroll
      for (int i = 0; i < 8; i++) a[i] = As[kk][ty * 8 + i];
#pragma unroll
      for (int j = 0; j < 4; j++) b[j] = Bs[kk][tx * 4 + j];
#pragma unroll
      for (int i = 0; i < 8; i++)
#pragma unroll
        for (int j = 0; j < 4; j++) acc[i][j] += a[i] * b[j];
    }
    __syncthreads();
  }

#pragma unroll
  for (int i = 0; i < 8; i++) {
    float* crow = Cc + (size_t)(bm + ty * 8 + i) * C_DIM + tx * 4;
    *reinterpret_cast<float4*>(crow) = make_float4(acc[i][0], acc[i][1], acc[i][2], acc[i][3]);
  }
}

// ========== hw = x @ w_w [2048x4]: one warp per row ====================
__global__ void hw_kernel(const float* __restrict__ x, const float* __restrict__ w_w) {
  int warp = (blockIdx.x * blockDim.x + threadIdx.x) >> 5;
  int lane = threadIdx.x & 31;
  if (warp >= S_LEN) return;
  const float4* xr = reinterpret_cast<const float4*>(x + (size_t)warp * D_DIM);
  const float4* wr = reinterpret_cast<const float4*>(w_w);
  float d0 = 0.f, d1 = 0.f, d2 = 0.f, d3 = 0.f;
  for (int i = lane; i < D_DIM / 4; i += 32) {
    float4 xv = xr[i];
    float4 w0 = wr[i * 4 + 0];
    float4 w1 = wr[i * 4 + 1];
    float4 w2 = wr[i * 4 + 2];
    float4 w3 = wr[i * 4 + 3];
    d0 += xv.x * w0.x + xv.y * w1.x + xv.z * w2.x + xv.w * w3.x;
    d1 += xv.x * w0.y + xv.y * w1.y + xv.z * w2.y + xv.w * w3.y;
    d2 += xv.x * w0.z + xv.y * w1.z + xv.z * w2.z + xv.w * w3.z;
    d3 += xv.x * w0.w + xv.y * w1.w + xv.z * w2.w + xv.w * w3.w;
  }
#pragma unroll
  for (int off = 16; off > 0; off >>= 1) {
    d0 += __shfl_down_sync(0xffffffffu, d0, off);
    d1 += __shfl_down_sync(0xffffffffu, d1, off);
    d2 += __shfl_down_sync(0xffffffffu, d2, off);
    d3 += __shfl_down_sync(0xffffffffu, d3, off);
  }
  if (lane == 0) {
    g_hw[warp * 4 + 0] = d0;
    g_hw[warp * 4 + 1] = d1;
    g_hw[warp * 4 + 2] = d2;
    g_hw[warp * 4 + 3] = d3;
  }
}

// ---------------- k_orig = mean over the M=4 tokens of each chunk -------
__global__ void kmean_kernel(const float* __restrict__ x) {
  int idx = blockIdx.x * 256 + threadIdx.x;
  if (idx >= NC_CH * D_DIM) return;
  int nc = idx / D_DIM, d = idx - nc * D_DIM;
  const float* p = x + (size_t)nc * 4 * D_DIM + d;
  g_ko[idx] = 0.25f * (p[0] + p[D_DIM] + p[2 * D_DIM] + p[3 * D_DIM]);
}

// ------------- compression softmax (over 8 candidates) + LayerNorm ------
__global__ void compress_kernel(const float* __restrict__ b_a,
                                const float* __restrict__ b_b,
                                const float* __restrict__ kvn_w,
                                const float* __restrict__ kvn_b) {
  int nc = blockIdx.x;
  int c = threadIdx.x;  // 64
  float lg[8], val[8];
#pragma unroll
  for (int m = 0; m < 4; m++) {
    int cur = (nc * 4 + m) * 64 + c;
    lg[4 + m] = g_za[cur] + b_a[m * 64 + c];
    val[4 + m] = g_ca[cur];
    if (nc > 0) {
      int prev = ((nc - 1) * 4 + m) * 64 + c;
      lg[m] = g_zb[prev] + b_b[m * 64 + c];
      val[m] = g_cb[prev];
    } else {
      lg[m] = -1e30f + b_b[m * 64 + c];
      val[m] = 0.f;
    }
  }
  float mx = lg[0];
#pragma unroll
  for (int i = 1; i < 8; i++) mx = fmaxf(mx, lg[i]);
  float se = 0.f, comp = 0.f;
#pragma unroll
  for (int i = 0; i < 8; i++) {
    float e = expf(lg[i] - mx);
    se += e;
    comp += e * val[i];
  }
  comp /= se;

  __shared__ float red[64];
  red[c] = comp;
  __syncthreads();
  for (int off = 32; off > 0; off >>= 1) {
    if (c < off) red[c] += red[c + off];
    __syncthreads();
  }
  float mu = red[0] * (1.f / 64.f);
  __syncthreads();
  float dv = comp - mu;
  red[c] = dv * dv;
  __syncthreads();
  for (int off = 32; off > 0; off >>= 1) {
    if (c < off) red[c] += red[c + off];
    __syncthreads();
  }
  float var = red[0] * (1.f / 64.f);
  g_kc[nc * 64 + c] = dv * rsqrtf(var + 1e-6f) * kvn_w[c] + kvn_b[c];
}

// ------------- per-(s,h) LayerNorm then RoPE on last 32 channels --------
__global__ void qln_rope_kernel(const float* __restrict__ qn_w,
                                const float* __restrict__ qn_b) {
  int s = blockIdx.x;
  int c = threadIdx.x;  // 64
  int h = threadIdx.y;  // 16
  float v = g_qf[(size_t)s * 1024 + h * 64 + c];
  __shared__ float red[16][64];
  __shared__ float lnb[16][65];
  red[h][c] = v;
  __syncthreads();
  for (int off = 32; off > 0; off >>= 1) {
    if (c < off) red[h][c] += red[h][c + off];
    __syncthreads();
  }
  float mu = red[h][0] * (1.f / 64.f);
  __syncthreads();
  float dv = v - mu;
  red[h][c] = dv * dv;
  __syncthreads();
  for (int off = 32; off > 0; off >>= 1) {
    if (c < off) red[h][c] += red[h][c + off];
    __syncthreads();
  }
  float var = red[h][0] * (1.f / 64.f);
  float ln = dv * rsqrtf(var + 1e-6f) * qn_w[c] + qn_b[c];
  lnb[h][c] = ln;
  __syncthreads();
  float outv;
  if (c < 32) {
    outv = ln;
  } else {
    int j = (c - 32) >> 1;
    float inv = exp2f(-(float)j * 0.830482023722f);  // 10000^(-j/16)
    float ang = (float)s * inv;
    float cs = cosf(ang), sn = sinf(ang);
    float x0 = lnb[h][32 + 2 * j], x1 = lnb[h][32 + 2 * j + 1];
    outv = ((c & 1) == 0) ? (x0 * cs - x1 * sn) : (x0 * sn + x1 * cs);
  }
  g_qf[(size_t)s * 1024 + h * 64 + c] = outv;
}

// ------------- indexer scores: relu(q_i . k_proj) weighted by hw --------
__global__ void iscore_kernel() {
  int s = blockIdx.x;
  __shared__ float qs[256];
  __shared__ float ws[4];
  int tid = threadIdx.x;  // 256
  qs[tid] = g_qi[(size_t)s * 256 + tid];
  if (tid < 4) ws[tid] = g_hw[s * 4 + tid];
  __syncthreads();
  const float4* qs4 = reinterpret_cast<const float4*>(qs);
  for (int k = tid; k < NC_CH; k += 256) {
    const float4* kr = reinterpret_cast<const float4*>(g_kp + k * 64);
    float d0 = 0.f, d1 = 0.f, d2 = 0.f, d3 = 0.f;
#pragma unroll
    for (int c4 = 0; c4 < 16; c4++) {
      float4 kv = kr[c4];
      float4 q0 = qs4[c4];
      float4 q1 = qs4[16 + c4];
      float4 q2 = qs4[32 + c4];
      float4 q3 = qs4[48 + c4];
      d0 += q0.x * kv.x + q0.y * kv.y + q0.z * kv.z + q0.w * kv.w;
      d1 += q1.x * kv.x + q1.y * kv.y + q1.z * kv.z + q1.w * kv.w;
      d2 += q2.x * kv.x + q2.y * kv.y + q2.z * kv.z + q2.w * kv.w;
      d3 += q3.x * kv.x + q3.y * kv.y + q3.z * kv.z + q3.w * kv.w;
    }
    float sc = fmaxf(d0, 0.f) * ws[0] + fmaxf(d1, 0.f) * ws[1] +
               fmaxf(d2, 0.f) * ws[2] + fmaxf(d3, 0.f) * ws[3];
    g_is[(size_t)s * NC_CH + k] = (k < s) ? sc : NEG_INF;
  }
}

// ------------- exact top-512: bitonic sort by (value desc, index asc) ---
__global__ __launch_bounds__(512) void topk_kernel() {
  int s = blockIdx.x, tid = threadIdx.x;  // 512
  __shared__ float v[1024];
  __shared__ int ix[1024];
  v[tid] = g_is[(size_t)s * 1024 + tid];
  ix[tid] = tid;
  v[tid + 512] = g_is[(size_t)s * 1024 + tid + 512];
  ix[tid + 512] = tid + 512;
  __syncthreads();
  for (int k = 2; k <= 1024; k <<= 1) {
    for (int j = k >> 1; j > 0; j >>= 1) {
      for (int t = tid; t < 1024; t += 512) {
        int p = t ^ j;
        if (p > t) {
          float va = v[t], vb = v[p];
          int ia = ix[t], ib = ix[p];
          bool before = (va > vb) || (va == vb && ia < ib);
          bool dir = ((t & k) == 0);
          if (before != dir) {
            v[t] = vb; v[p] = va;
            ix[t] = ib; ix[p] = ia;
          }
        }
      }
      __syncthreads();
    }
  }
  g_ti[(size_t)s * 512 + tid] = ix[tid];
}

// ------------- gathered sparse attention (4 quarters of 128 chunks) -----
__global__ __launch_bounds__(256) void attn_kernel(const float* __restrict__ sink) {
  const int s = blockIdx.x, tid = threadIdx.x;  // 256
  __shared__ float qs[1024];
  __shared__ float Ks[128][68];
  __shared__ float ew[16][128];
  __shared__ float denom[16];

#pragma unroll
  for (int i = 0; i < 4; i++) qs[tid + 256 * i] = g_qf[(size_t)s * 1024 + tid + 256 * i];
  if (tid < 16) denom[tid] = __expf(sink[tid]);
  __syncthreads();

  const int c = tid & 63, g = tid >> 6;
  float acc0 = 0.f, acc1 = 0.f, acc2 = 0.f, acc3 = 0.f;
  const float4* qs4 = reinterpret_cast<const float4*>(qs);
  const int* trow = g_ti + (size_t)s * 512;

  for (int qtr = 0; qtr < 4; qtr++) {
    if (qtr) __syncthreads();

    {
      int j = tid >> 1, p = tid & 1;
      int ck = trow[qtr * 128 + j];
      const float4* src = reinterpret_cast<const float4*>(g_kc + ck * 64);
      float4* dst = reinterpret_cast<float4*>(&Ks[j][0]);
#pragma unroll
      for (int q = 0; q < 8; q++) dst[p + 2 * q] = src[p + 2 * q];
    }
    __syncthreads();

    {
      int kk = tid >> 1, hh = (tid & 1) * 8;
      int ck = trow[qtr * 128 + kk];
      bool valid = (s < ck * 4);
      const float4* kr = reinterpret_cast<const float4*>(&Ks[kk][0]);
      float d[8];
#pragma unroll
      for (int h = 0; h < 8; h++) d[h] = 0.f;
#pragma unroll
      for (int c4 = 0; c4 < 16; c4++) {
        float4 kv = kr[c4];
#pragma unroll
        for (int h = 0; h < 8; h++) {
          float4 qv = qs4[(hh + h) * 16 + c4];
          d[h] += qv.x * kv.x + qv.y * kv.y + qv.z * kv.z + qv.w * kv.w;
        }
      }
#pragma unroll
      for (int h = 0; h < 8; h++) ew[hh + h][kk] = valid ? __expf(d[h] * 0.125f) : 0.f;
    }
    __syncthreads();

    {
      int h = tid >> 4, seg = tid & 15;
      float p = 0.f;
#pragma unroll
      for (int k = 0; k < 8; k++) p += ew[h][seg * 8 + k];
#pragma unroll
      for (int off = 8; off > 0; off >>= 1) p += __shfl_down_sync(0xffffffffu, p, off);
      if (seg == 0) denom[h] += p;
    }

    for (int k = 0; k < 128; k++) {
      float kv = Ks[k][c];
      acc0 += ew[g][k] * kv;
      acc1 += ew[g + 4][k] * kv;
      acc2 += ew[g + 8][k] * kv;
      acc3 += ew[g + 12][k] * kv;
    }
  }
  __syncthreads();

  g_ao[(size_t)s * 1024 + (g) * 64 + c] = acc0 / denom[g];
  g_ao[(size_t)s * 1024 + (g + 4) * 64 + c] = acc1 / denom[g + 4];
  g_ao[(size_t)s * 1024 + (g + 8) * 64 + c] = acc2 / denom[g + 8];
  g_ao[(size_t)s * 1024 + (g + 12) * 64 + c] = acc3 / denom[g + 12];
}

// ---------------------------- launcher ----------------------------------
extern "C" void kernel_launch(void* const* d_in, const int* in_sizes, int n_in,
                              void* d_out, int out_size) {
  (void)in_sizes; (void)n_in; (void)out_size;
  const float* x      = (const float*)d_in[0];
  const float* w_kva  = (const float*)d_in[1];
  const float* w_kvb  = (const float*)d_in[2];
  const float* w_za   = (const float*)d_in[3];
  const float* w_zb   = (const float*)d_in[4];
  const float* b_a    = (const float*)d_in[5];
  const float* b_b    = (const float*)d_in[6];
  const float* w_dq   = (const float*)d_in[7];
  const float* w_iuq  = (const float*)d_in[8];
  const float* w_w    = (const float*)d_in[9];
  const float* w_k    = (const float*)d_in[10];
  const float* w_uq   = (const float*)d_in[11];
  const float* o_down = (const float*)d_in[12];
  const float* o_up   = (const float*)d_in[13];
  const float* kvn_w  = (const float*)d_in[14];
  const float* kvn_b  = (const float*)d_in[15];
  const float* qn_w   = (const float*)d_in[16];
  const float* qn_b   = (const float*)d_in[17];
  const float* sink   = (const float*)d_in[18];
  float* out = (float*)d_out;

  void *p_ca, *p_cb, *p_za, *p_zb, *p_cq, *p_qi, *p_ko, *p_kp, *p_qf, *p_ao, *p_gb;
  cudaGetSymbolAddress(&p_ca, g_ca);
  cudaGetSymbolAddress(&p_cb, g_cb);
  cudaGetSymbolAddress(&p_za, g_za);
  cudaGetSymbolAddress(&p_zb, g_zb);
  cudaGetSymbolAddress(&p_cq, g_cq);
  cudaGetSymbolAddress(&p_qi, g_qi);
  cudaGetSymbolAddress(&p_ko, g_ko);
  cudaGetSymbolAddress(&p_kp, g_kp);
  cudaGetSymbolAddress(&p_qf, g_qf);
  cudaGetSymbolAddress(&p_ao, g_ao);
  cudaGetSymbolAddress(&p_gb, g_gb);

  auto grid2 = [](int M, int N) { return dim3((unsigned)(N / 128), (unsigned)(M / 128), 1u); };

  // chunk means first (feeds k_proj inside fused projections)
  kmean_kernel<<<(NC_CH * D_DIM + 255) / 256, 256>>>(x);

  // fused narrow projections
  ProjArgs pa;
  pa.A[0] = x;     pa.B[0] = w_kva; pa.Cc[0] = (float*)p_ca; pa.M[0] = S_LEN;
  pa.A[1] = x;     pa.B[1] = w_kvb; pa.Cc[1] = (float*)p_cb; pa.M[1] = S_LEN;
  pa.A[2] = x;     pa.B[2] = w_za;  pa.Cc[2] = (float*)p_za; pa.M[2] = S_LEN;
  pa.A[3] = x;     pa.B[3] = w_zb;  pa.Cc[3] = (float*)p_zb; pa.M[3] = S_LEN;
  pa.A[4] = (const float*)p_ko; pa.B[4] = w_k; pa.Cc[4] = (float*)p_kp; pa.M[4] = NC_CH;
  proj64_kernel<<<dim3(5, S_LEN / 128), 256>>>(pa);

  // hw = x @ w_w
  hw_kernel<<<S_LEN / 8, 256>>>(x, w_w);

  // c_q = x @ w_dq  (fp32 — feeds the discrete top-k path)
  sgemm_kernel<<<grid2(S_LEN, DC_N), 256>>>(x, w_dq, (float*)p_cq, D_DIM, D_DIM, DC_N, DC_N, 0, 0, 0);

  // chunk compression + LN(kc)
  compress_kernel<<<NC_CH, 64>>>(b_a, b_b, kvn_w, kvn_b);

  // indexer path (fp32 — discrete)
  sgemm_kernel<<<grid2(S_LEN, NHI_N * CI_N), 256>>>((const float*)p_cq, w_iuq, (float*)p_qi,
                                                    DC_N, DC_N, NHI_N * CI_N, NHI_N * CI_N, 0, 0, 0);
  iscore_kernel<<<S_LEN, 256>>>();
  topk_kernel<<<S_LEN, 512>>>();

  // q path (tensor bf16 3x — continuous), then LN + rope in-place
  tgemm_kernel<<<grid2(S_LEN, NH_N * C_DIM), 256>>>((const float*)p_cq, w_uq, (float*)p_qf,
                                                    DC_N, DC_N, NH_N * C_DIM, NH_N * C_DIM, 0, 0, 0);
  qln_rope_kernel<<<S_LEN, dim3(64, 16)>>>(qn_w, qn_b);

  // sparse attention over top-k compressed chunks
  attn_kernel<<<S_LEN, 256>>>(sink);

  // grouped o_down: ONE batched launch (z = group), tensor
  tgemm_kernel<<<dim3(DG_N / 128, S_LEN / 128, NG_N), 256>>>(
      (const float*)p_ao, o_down, (float*)p_gb,
      256, NH_N * C_DIM, DG_N, NG_N * DG_N,
      /*sA=*/256, /*sB=*/(long)256 * DG_N, /*sC=*/DG_N);

  // o_up (tensor)
  tgemm_kernel<<<grid2(S_LEN, D_DIM), 256>>>((const float*)p_gb, o_up, out,
                                             NG_N * DG_N, NG_N * DG_N, D_DIM, D_DIM, 0, 0, 0);
}

// round 9
// speedup vs baseline: 1.9291x; 1.0102x over previous
#include <cuda_runtime.h>
#include <cuda_bf16.h>
#include <cstdint>
#include <cstddef>

// ---------------- problem constants ----------------
#define S_LEN   4096
#define D_DIM   2048
#define C_DIM   64
#define M_CH    4
#define NC_CH   1024
#define TOPK_N  512
#define NH_N    16
#define DC_N    512
#define NHI_N   4
#define CI_N    64
#define NG_N    4
#define DG_N    512

#define NEG_INF (__int_as_float(0xff800000))

// ---------------- scratch (device globals; no allocation allowed) -------
__device__ float g_ca[S_LEN * C_DIM];
__device__ float g_cb[S_LEN * C_DIM];
__device__ float g_za[S_LEN * C_DIM];
__device__ float g_zb[S_LEN * C_DIM];
__device__ float g_kc[NC_CH * C_DIM];
__device__ float g_cq[S_LEN * DC_N];
__device__ float g_qi[S_LEN * NHI_N * CI_N];
__device__ float g_hw[S_LEN * NHI_N];
__device__ float g_ko[NC_CH * D_DIM];
__device__ float g_kp[NC_CH * CI_N];
__device__ float g_qf[S_LEN * NH_N * C_DIM];
__device__ float g_is[(size_t)S_LEN * NC_CH];
__device__ int   g_ti[S_LEN * TOPK_N];
__device__ float g_ao[S_LEN * NH_N * C_DIM];
__device__ float g_gb[(size_t)S_LEN * NG_N * DG_N];

// ---------------- bf16 helpers ----------------
__device__ __forceinline__ uint32_t pack_bf16(float e0, float e1) {
  uint32_t d;
  asm("cvt.rn.bf16x2.f32 %0, %1, %2;" : "=r"(d) : "f"(e1), "f"(e0));
  return d;
}

__device__ __forceinline__ void split_pair(float a0, float a1, uint32_t& hp, uint32_t& lp) {
  hp = pack_bf16(a0, a1);
  float r0 = a0 - __uint_as_float(hp << 16);
  float r1 = a1 - __uint_as_float(hp & 0xffff0000u);
  lp = pack_bf16(r0, r1);
}

__device__ __forceinline__ void mma_bf16(float* c, const uint32_t* a, const uint32_t* b) {
  asm volatile(
      "mma.sync.aligned.m16n8k16.row.col.f32.bf16.bf16.f32 "
      "{%0,%1,%2,%3}, {%4,%5,%6,%7}, {%8,%9}, {%0,%1,%2,%3};"
      : "+f"(c[0]), "+f"(c[1]), "+f"(c[2]), "+f"(c[3])
      : "r"(a[0]), "r"(a[1]), "r"(a[2]), "r"(a[3]), "r"(b[0]), "r"(b[1]));
}

// ========== tensor GEMM, bf16 3-term split, double-buffered planes ======
// C = A(MxK) @ B(KxN). 128x128 tile, BK=16, 256 threads (8 warps 2x4),
// per-warp 64x32 via m16n8k16. ONE sync per K-slab. Batched via blockIdx.z.
__global__ __launch_bounds__(256) void tgemm_kernel(
    const float* __restrict__ A, const float* __restrict__ B,
    float* __restrict__ Cc, int K, int lda, int ldb, int ldc,
    long sA, long sB, long sC) {
  A += (long)blockIdx.z * sA;
  B += (long)blockIdx.z * sB;
  Cc += (long)blockIdx.z * sC;

  __shared__ uint32_t Ah[2][128][12], Al[2][128][12];
  __shared__ uint32_t Bh[2][8][136], Bl[2][8][136];

  const int bm = blockIdx.y * 128;
  const int bn = blockIdx.x * 128;
  const int tid = threadIdx.x;
  const int warp = tid >> 5, lane = tid & 31;
  const int wm = warp >> 2, wn = warp & 3;
  const int g = lane >> 2, t = lane & 3;

  const int arow = tid >> 1, akoff = (tid & 1) * 8;
  const int brp = tid >> 5, bcol = lane * 4;

  const float* Aptr = A + (size_t)(bm + arow) * lda + akoff;
  const float* Bptr0 = B + (size_t)(2 * brp) * ldb + bn + bcol;
  const float* Bptr1 = Bptr0 + ldb;

  float acc[4][4][4];
#pragma unroll
  for (int i = 0; i < 4; i++)
#pragma unroll
    for (int j = 0; j < 4; j++)
#pragma unroll
      for (int r = 0; r < 4; r++) acc[i][j][r] = 0.f;

  // preload + convert slab 0 into buffer 0
  float4 av0 = *reinterpret_cast<const float4*>(Aptr);
  float4 av1 = *reinterpret_cast<const float4*>(Aptr + 4);
  float4 bv0 = *reinterpret_cast<const float4*>(Bptr0);
  float4 bv1 = *reinterpret_cast<const float4*>(Bptr1);
  {
    uint32_t h[4], l[4];
    split_pair(av0.x, av0.y, h[0], l[0]);
    split_pair(av0.z, av0.w, h[1], l[1]);
    split_pair(av1.x, av1.y, h[2], l[2]);
    split_pair(av1.z, av1.w, h[3], l[3]);
    int ac = akoff >> 1;
    *reinterpret_cast<uint4*>(&Ah[0][arow][ac]) = make_uint4(h[0], h[1], h[2], h[3]);
    *reinterpret_cast<uint4*>(&Al[0][arow][ac]) = make_uint4(l[0], l[1], l[2], l[3]);
    uint32_t bh[4], bl[4];
    split_pair(bv0.x, bv1.x, bh[0], bl[0]);
    split_pair(bv0.y, bv1.y, bh[1], bl[1]);
    split_pair(bv0.z, bv1.z, bh[2], bl[2]);
    split_pair(bv0.w, bv1.w, bh[3], bl[3]);
    *reinterpret_cast<uint4*>(&Bh[0][brp][bcol]) = make_uint4(bh[0], bh[1], bh[2], bh[3]);
    *reinterpret_cast<uint4*>(&Bl[0][brp][bcol]) = make_uint4(bl[0], bl[1], bl[2], bl[3]);
  }
  __syncthreads();

  int buf = 0;
  for (int k0 = 0; k0 < K; k0 += 16) {
    const bool more = (k0 + 16 < K);
    if (more) {  // prefetch next slab into regs (overlaps compute)
      av0 = *reinterpret_cast<const float4*>(Aptr + k0 + 16);
      av1 = *reinterpret_cast<const float4*>(Aptr + k0 + 20);
      bv0 = *reinterpret_cast<const float4*>(Bptr0 + (size_t)(k0 + 16) * ldb);
      bv1 = *reinterpret_cast<const float4*>(Bptr1 + (size_t)(k0 + 16) * ldb);
    }

    // compute from buf
    {
      uint32_t bhf[4][2], blf[4][2];
#pragma unroll
      for (int ni = 0; ni < 4; ni++) {
        int colB = wn * 32 + ni * 8 + g;
        bhf[ni][0] = Bh[buf][t][colB];
        bhf[ni][1] = Bh[buf][t + 4][colB];
        blf[ni][0] = Bl[buf][t][colB];
        blf[ni][1] = Bl[buf][t + 4][colB];
      }
#pragma unroll
      for (int mi = 0; mi < 4; mi++) {
        int rowA = wm * 64 + mi * 16 + g;
        uint32_t ah[4], al[4];
        ah[0] = Ah[buf][rowA][t];
        ah[1] = Ah[buf][rowA + 8][t];
        ah[2] = Ah[buf][rowA][t + 4];
        ah[3] = Ah[buf][rowA + 8][t + 4];
        al[0] = Al[buf][rowA][t];
        al[1] = Al[buf][rowA + 8][t];
        al[2] = Al[buf][rowA][t + 4];
        al[3] = Al[buf][rowA + 8][t + 4];
#pragma unroll
        for (int ni = 0; ni < 4; ni++) mma_bf16(acc[mi][ni], ah, bhf[ni]);
#pragma unroll
        for (int ni = 0; ni < 4; ni++) mma_bf16(acc[mi][ni], ah, blf[ni]);
#pragma unroll
        for (int ni = 0; ni < 4; ni++) mma_bf16(acc[mi][ni], al, bhf[ni]);
      }
    }

    if (more) {  // convert+store next slab into other buffer, ONE sync
      int nb = buf ^ 1;
      uint32_t h[4], l[4];
      split_pair(av0.x, av0.y, h[0], l[0]);
      split_pair(av0.z, av0.w, h[1], l[1]);
      split_pair(av1.x, av1.y, h[2], l[2]);
      split_pair(av1.z, av1.w, h[3], l[3]);
      int ac = akoff >> 1;
      *reinterpret_cast<uint4*>(&Ah[nb][arow][ac]) = make_uint4(h[0], h[1], h[2], h[3]);
      *reinterpret_cast<uint4*>(&Al[nb][arow][ac]) = make_uint4(l[0], l[1], l[2], l[3]);
      uint32_t bh[4], bl[4];
      split_pair(bv0.x, bv1.x, bh[0], bl[0]);
      split_pair(bv0.y, bv1.y, bh[1], bl[1]);
      split_pair(bv0.z, bv1.z, bh[2], bl[2]);
      split_pair(bv0.w, bv1.w, bh[3], bl[3]);
      *reinterpret_cast<uint4*>(&Bh[nb][brp][bcol]) = make_uint4(bh[0], bh[1], bh[2], bh[3]);
      *reinterpret_cast<uint4*>(&Bl[nb][brp][bcol]) = make_uint4(bl[0], bl[1], bl[2], bl[3]);
      __syncthreads();
      buf = nb;
    }
  }

  // epilogue
#pragma unroll
  for (int mi = 0; mi < 4; mi++) {
    int row0 = bm + wm * 64 + mi * 16 + g;
#pragma unroll
    for (int ni = 0; ni < 4; ni++) {
      int col = bn + wn * 32 + ni * 8 + 2 * t;
      *reinterpret_cast<float2*>(Cc + (size_t)row0 * ldc + col) =
          make_float2(acc[mi][ni][0], acc[mi][ni][1]);
      *reinterpret_cast<float2*>(Cc + (size_t)(row0 + 8) * ldc + col) =
          make_float2(acc[mi][ni][2], acc[mi][ni][3]);
    }
  }
}

// ========== fp32 SGEMM (R4-exact) — DISCRETE-feeding path (c_q, q_i) ====
__global__ __launch_bounds__(256, 2) void sgemm_kernel(
    const float* __restrict__ A, const float* __restrict__ B,
    float* __restrict__ Cc, int K, int lda, int ldb, int ldc,
    long sA, long sB, long sC) {
  A += (long)blockIdx.z * sA;
  B += (long)blockIdx.z * sB;
  Cc += (long)blockIdx.z * sC;

  __shared__ float As[2][8][128];
  __shared__ float Bs[2][8][132];
  const int bm = blockIdx.y * 128;
  const int bn = blockIdx.x * 128;
  const int tid = threadIdx.x;
  const int tx = tid & 15, ty = tid >> 4;
  const int arow = tid >> 1, acol = (tid & 1) * 4;
  const int brow = tid >> 5, bcol = (tid & 31) * 4;

  const float* Aptr = A + (size_t)(bm + arow) * lda + acol;
  const float* Bptr = B + (size_t)brow * ldb + bn + bcol;

  float acc[8][8];
#pragma unroll
  for (int i = 0; i < 8; i++)
#pragma unroll
    for (int j = 0; j < 8; j++) acc[i][j] = 0.f;

  {
    float4 av = *reinterpret_cast<const float4*>(Aptr);
    float4 bv = *reinterpret_cast<const float4*>(Bptr);
    As[0][acol + 0][arow] = av.x;
    As[0][acol + 1][arow] = av.y;
    As[0][acol + 2][arow] = av.z;
    As[0][acol + 3][arow] = av.w;
    Bs[0][brow][bcol + 0] = bv.x;
    Bs[0][brow][bcol + 1] = bv.y;
    Bs[0][brow][bcol + 2] = bv.z;
    Bs[0][brow][bcol + 3] = bv.w;
  }
  __syncthreads();

  int buf = 0;
  for (int k0 = 0; k0 < K; k0 += 8) {
    float4 av, bv;
    const bool more = (k0 + 8 < K);
    if (more) {
      av = *reinterpret_cast<const float4*>(Aptr + k0 + 8);
      bv = *reinterpret_cast<const float4*>(Bptr + (size_t)(k0 + 8) * ldb);
    }
#pragma unroll
    for (int kk = 0; kk < 8; kk++) {
      float a[8], b[8];
#pragma unroll
      for (int i = 0; i < 8; i++) a[i] = As[buf][kk][ty * 8 + i];
#pragma unroll
      for (int j = 0; j < 8; j++) b[j] = Bs[buf][kk][tx * 8 + j];
#pragma unroll
      for (int i = 0; i < 8; i++)
#pragma unroll
        for (int j = 0; j < 8; j++) acc[i][j] += a[i] * b[j];
    }
    if (more) {
      int nb = buf ^ 1;
      As[nb][acol + 0][arow] = av.x;
      As[nb][acol + 1][arow] = av.y;
      As[nb][acol + 2][arow] = av.z;
      As[nb][acol + 3][arow] = av.w;
      Bs[nb][brow][bcol + 0] = bv.x;
      Bs[nb][brow][bcol + 1] = bv.y;
      Bs[nb][brow][bcol + 2] = bv.z;
      Bs[nb][brow][bcol + 3] = bv.w;
      __syncthreads();
      buf = nb;
    }
  }

#pragma unroll
  for (int i = 0; i < 8; i++) {
    float* crow = Cc + (size_t)(bm + ty * 8 + i) * ldc + bn + tx * 8;
    *reinterpret_cast<float4*>(crow) = make_float4(acc[i][0], acc[i][1], acc[i][2], acc[i][3]);
    *reinterpret_cast<float4*>(crow + 4) = make_float4(acc[i][4], acc[i][5], acc[i][6], acc[i][7]);
  }
}

// ========== fused narrow projections: 5 independent (A @ B[2048x64]) ====
struct ProjArgs {
  const float* A[5];
  const float* B[5];
  float* Cc[5];
  int M[5];
};

__global__ __launch_bounds__(256, 2) void proj64_kernel(ProjArgs pa) {
  const int mat = blockIdx.x;
  const int bm = blockIdx.y * 128;
  if (bm >= pa.M[mat]) return;
  const float* A = pa.A[mat];
  const float* B = pa.B[mat];
  float* Cc = pa.Cc[mat];

  __shared__ float As[8][128];
  __shared__ float Bs[8][68];
  const int tid = threadIdx.x;
  const int tx = tid & 15, ty = tid >> 4;
  const int arow = tid >> 1, acol = (tid & 1) * 4;
  const int brow = tid >> 4, bcol = (tid & 15) * 4;
  const bool bload = (tid < 128);

  const float* Aptr = A + (size_t)(bm + arow) * D_DIM + acol;
  const float* Bptr = B + (size_t)brow * C_DIM + bcol;

  float acc[8][4];
#pragma unroll
  for (int i = 0; i < 8; i++)
#pragma unroll
    for (int j = 0; j < 4; j++) acc[i][j] = 0.f;

  float4 av = *reinterpret_cast<const float4*>(Aptr);
  float4 bv = bload ? *reinterpret_cast<const float4*>(Bptr) : make_float4(0, 0, 0, 0);

  for (int k0 = 0; k0 < D_DIM; k0 += 8) {
    As[acol + 0][arow] = av.x;
    As[acol + 1][arow] = av.y;
    As[acol + 2][arow] = av.z;
    As[acol + 3][arow] = av.w;
    if (bload) {
      Bs[brow][bcol + 0] = bv.x;
      Bs[brow][bcol + 1] = bv.y;
      Bs[brow][bcol + 2] = bv.z;
      Bs[brow][bcol + 3] = bv.w;
    }
    __syncthreads();

    if (k0 + 8 < D_DIM) {
      av = *reinterpret_cast<const float4*>(Aptr + k0 + 8);
      if (bload) bv = *reinterpret_cast<const float4*>(Bptr + (size_t)(k0 + 8) * C_DIM);
    }

#pragma unroll
    for (int kk = 0; kk < 8; kk++) {
      float a[8], b[4];
#pragma unroll
      for (int i = 0; i < 8; i++) a[i] = As[kk][ty * 8 + i];
#pragma unroll
      for (int j = 0; j < 4; j++) b[j] = Bs[kk][tx * 4 + j];
#pragma unroll
      for (int i = 0; i < 8; i++)
#pragma unroll
        for (int j = 0; j < 4; j++) acc[i][j] += a[i] * b[j];
    }
    __syncthreads();
  }

#pragma unroll
  for (int i = 0; i < 8; i++) {
    float* crow = Cc + (size_t)(bm + ty * 8 + i) * C_DIM + tx * 4;
    *reinterpret_cast<float4*>(crow) = make_float4(acc[i][0], acc[i][1], acc[i][2], acc[i][3]);
  }
}

// ========== hw = x @ w_w [2048x4]: one warp per row ====================
__global__ void hw_kernel(const float* __restrict__ x, const float* __restrict__ w_w) {
  int warp = (blockIdx.x * blockDim.x + threadIdx.x) >> 5;
  int lane = threadIdx.x & 31;
  if (warp >= S_LEN) return;
  const float4* xr = reinterpret_cast<const float4*>(x + (size_t)warp * D_DIM);
  const float4* wr = reinterpret_cast<const float4*>(w_w);
  float d0 = 0.f, d1 = 0.f, d2 = 0.f, d3 = 0.f;
  for (int i = lane; i < D_DIM / 4; i += 32) {
    float4 xv = xr[i];
    float4 w0 = wr[i * 4 + 0];
    float4 w1 = wr[i * 4 + 1];
    float4 w2 = wr[i * 4 + 2];
    float4 w3 = wr[i * 4 + 3];
    d0 += xv.x * w0.x + xv.y * w1.x + xv.z * w2.x + xv.w * w3.x;
    d1 += xv.x * w0.y + xv.y * w1.y + xv.z * w2.y + xv.w * w3.y;
    d2 += xv.x * w0.z + xv.y * w1.z + xv.z * w2.z + xv.w * w3.z;
    d3 += xv.x * w0.w + xv.y * w1.w + xv.z * w2.w + xv.w * w3.w;
  }
#pragma unroll
  for (int off = 16; off > 0; off >>= 1) {
    d0 += __shfl_down_sync(0xffffffffu, d0, off);
    d1 += __shfl_down_sync(0xffffffffu, d1, off);
    d2 += __shfl_down_sync(0xffffffffu, d2, off);
    d3 += __shfl_down_sync(0xffffffffu, d3, off);
  }
  if (lane == 0) {
    g_hw[warp * 4 + 0] = d0;
    g_hw[warp * 4 + 1] = d1;
    g_hw[warp * 4 + 2] = d2;
    g_hw[warp * 4 + 3] = d3;
  }
}

// ---------------- k_orig = mean over the M=4 tokens of each chunk -------
__global__ void kmean_kernel(const float* __restrict__ x) {
  int idx = blockIdx.x * 256 + threadIdx.x;
  if (idx >= NC_CH * D_DIM) return;
  int nc = idx / D_DIM, d = idx - nc * D_DIM;
  const float* p = x + (size_t)nc * 4 * D_DIM + d;
  g_ko[idx] = 0.25f * (p[0] + p[D_DIM] + p[2 * D_DIM] + p[3 * D_DIM]);
}

// ------------- compression softmax (over 8 candidates) + LayerNorm ------
__global__ void compress_kernel(const float* __restrict__ b_a,
                                const float* __restrict__ b_b,
                                const float* __restrict__ kvn_w,
                                const float* __restrict__ kvn_b) {
  int nc = blockIdx.x;
  int c = threadIdx.x;  // 64
  float lg[8], val[8];
#pragma unroll
  for (int m = 0; m < 4; m++) {
    int cur = (nc * 4 + m) * 64 + c;
    lg[4 + m] = g_za[cur] + b_a[m * 64 + c];
    val[4 + m] = g_ca[cur];
    if (nc > 0) {
      int prev = ((nc - 1) * 4 + m) * 64 + c;
      lg[m] = g_zb[prev] + b_b[m * 64 + c];
      val[m] = g_cb[prev];
    } else {
      lg[m] = -1e30f + b_b[m * 64 + c];
      val[m] = 0.f;
    }
  }
  float mx = lg[0];
#pragma unroll
  for (int i = 1; i < 8; i++) mx = fmaxf(mx, lg[i]);
  float se = 0.f, comp = 0.f;
#pragma unroll
  for (int i = 0; i < 8; i++) {
    float e = expf(lg[i] - mx);
    se += e;
    comp += e * val[i];
  }
  comp /= se;

  __shared__ float red[64];
  red[c] = comp;
  __syncthreads();
  for (int off = 32; off > 0; off >>= 1) {
    if (c < off) red[c] += red[c + off];
    __syncthreads();
  }
  float mu = red[0] * (1.f / 64.f);
  __syncthreads();
  float dv = comp - mu;
  red[c] = dv * dv;
  __syncthreads();
  for (int off = 32; off > 0; off >>= 1) {
    if (c < off) red[c] += red[c + off];
    __syncthreads();
  }
  float var = red[0] * (1.f / 64.f);
  g_kc[nc * 64 + c] = dv * rsqrtf(var + 1e-6f) * kvn_w[c] + kvn_b[c];
}

// ------------- per-(s,h) LayerNorm then RoPE on last 32 channels --------
__global__ void qln_rope_kernel(const float* __restrict__ qn_w,
                                const float* __restrict__ qn_b) {
  int s = blockIdx.x;
  int c = threadIdx.x;  // 64
  int h = threadIdx.y;  // 16
  float v = g_qf[(size_t)s * 1024 + h * 64 + c];
  __shared__ float red[16][64];
  __shared__ float lnb[16][65];
  red[h][c] = v;
  __syncthreads();
  for (int off = 32; off > 0; off >>= 1) {
    if (c < off) red[h][c] += red[h][c + off];
    __syncthreads();
  }
  float mu = red[h][0] * (1.f / 64.f);
  __syncthreads();
  float dv = v - mu;
  red[h][c] = dv * dv;
  __syncthreads();
  for (int off = 32; off > 0; off >>= 1) {
    if (c < off) red[h][c] += red[h][c + off];
    __syncthreads();
  }
  float var = red[h][0] * (1.f / 64.f);
  float ln = dv * rsqrtf(var + 1e-6f) * qn_w[c] + qn_b[c];
  lnb[h][c] = ln;
  __syncthreads();
  float outv;
  if (c < 32) {
    outv = ln;
  } else {
    int j = (c - 32) >> 1;
    float inv = exp2f(-(float)j * 0.830482023722f);  // 10000^(-j/16)
    float ang = (float)s * inv;
    float cs = cosf(ang), sn = sinf(ang);
    float x0 = lnb[h][32 + 2 * j], x1 = lnb[h][32 + 2 * j + 1];
    outv = ((c & 1) == 0) ? (x0 * cs - x1 * sn) : (x0 * sn + x1 * cs);
  }
  g_qf[(size_t)s * 1024 + h * 64 + c] = outv;
}

// ------------- indexer scores: relu(q_i . k_proj) weighted by hw --------
__global__ void iscore_kernel() {
  int s = blockIdx.x;
  __shared__ float qs[256];
  __shared__ float ws[4];
  int tid = threadIdx.x;  // 256
  qs[tid] = g_qi[(size_t)s * 256 + tid];
  if (tid < 4) ws[tid] = g_hw[s * 4 + tid];
  __syncthreads();
  const float4* qs4 = reinterpret_cast<const float4*>(qs);
  for (int k = tid; k < NC_CH; k += 256) {
    const float4* kr = reinterpret_cast<const float4*>(g_kp + k * 64);
    float d0 = 0.f, d1 = 0.f, d2 = 0.f, d3 = 0.f;
#pragma unroll
    for (int c4 = 0; c4 < 16; c4++) {
      float4 kv = kr[c4];
      float4 q0 = qs4[c4];
      float4 q1 = qs4[16 + c4];
      float4 q2 = qs4[32 + c4];
      float4 q3 = qs4[48 + c4];
      d0 += q0.x * kv.x + q0.y * kv.y + q0.z * kv.z + q0.w * kv.w;
      d1 += q1.x * kv.x + q1.y * kv.y + q1.z * kv.z + q1.w * kv.w;
      d2 += q2.x * kv.x + q2.y * kv.y + q2.z * kv.z + q2.w * kv.w;
      d3 += q3.x * kv.x + q3.y * kv.y + q3.z * kv.z + q3.w * kv.w;
    }
    float sc = fmaxf(d0, 0.f) * ws[0] + fmaxf(d1, 0.f) * ws[1] +
               fmaxf(d2, 0.f) * ws[2] + fmaxf(d3, 0.f) * ws[3];
    g_is[(size_t)s * NC_CH + k] = (k < s) ? sc : NEG_INF;
  }
}

// ------------- exact top-512: bitonic sort by (value desc, index asc) ---
__global__ __launch_bounds__(512) void topk_kernel() {
  int s = blockIdx.x, tid = threadIdx.x;  // 512
  __shared__ float v[1024];
  __shared__ int ix[1024];
  v[tid] = g_is[(size_t)s * 1024 + tid];
  ix[tid] = tid;
  v[tid + 512] = g_is[(size_t)s * 1024 + tid + 512];
  ix[tid + 512] = tid + 512;
  __syncthreads();
  for (int k = 2; k <= 1024; k <<= 1) {
    for (int j = k >> 1; j > 0; j >>= 1) {
      for (int t = tid; t < 1024; t += 512) {
        int p = t ^ j;
        if (p > t) {
          float va = v[t], vb = v[p];
          int ia = ix[t], ib = ix[p];
          bool before = (va > vb) || (va == vb && ia < ib);
          bool dir = ((t & k) == 0);
          if (before != dir) {
            v[t] = vb; v[p] = va;
            ix[t] = ib; ix[p] = ia;
          }
        }
      }
      __syncthreads();
    }
  }
  g_ti[(size_t)s * 512 + tid] = ix[tid];
}

// ------------- gathered sparse attention (4 quarters of 128 chunks) -----
__global__ __launch_bounds__(256) void attn_kernel(const float* __restrict__ sink) {
  const int s = blockIdx.x, tid = threadIdx.x;  // 256
  __shared__ float qs[1024];
  __shared__ float Ks[128][68];
  __shared__ float ew[16][128];
  __shared__ float denom[16];

#pragma unroll
  for (int i = 0; i < 4; i++) qs[tid + 256 * i] = g_qf[(size_t)s * 1024 + tid + 256 * i];
  if (tid < 16) denom[tid] = __expf(sink[tid]);
  __syncthreads();

  const int c = tid & 63, g = tid >> 6;
  float acc0 = 0.f, acc1 = 0.f, acc2 = 0.f, acc3 = 0.f;
  const float4* qs4 = reinterpret_cast<const float4*>(qs);
  const int* trow = g_ti + (size_t)s * 512;

  for (int qtr = 0; qtr < 4; qtr++) {
    if (qtr) __syncthreads();

    // stage 128 gathered K rows: 2 threads per row, 8 float4 each
    {
      int j = tid >> 1, p = tid & 1;
      int ck = trow[qtr * 128 + j];
      const float4* src = reinterpret_cast<const float4*>(g_kc + ck * 64);
      float4* dst = reinterpret_cast<float4*>(&Ks[j][0]);
#pragma unroll
      for (int q = 0; q < 8; q++) dst[p + 2 * q] = src[p + 2 * q];
    }
    __syncthreads();

    // phase 1: scores -> exp; 2 threads per chunk, 8 heads each
    {
      int kk = tid >> 1, hh = (tid & 1) * 8;
      int ck = trow[qtr * 128 + kk];
      bool valid = (s < ck * 4);
      const float4* kr = reinterpret_cast<const float4*>(&Ks[kk][0]);
      float d[8];
#pragma unroll
      for (int h = 0; h < 8; h++) d[h] = 0.f;
#pragma unroll
      for (int c4 = 0; c4 < 16; c4++) {
        float4 kv = kr[c4];
#pragma unroll
        for (int h = 0; h < 8; h++) {
          float4 qv = qs4[(hh + h) * 16 + c4];
          d[h] += qv.x * kv.x + qv.y * kv.y + qv.z * kv.z + qv.w * kv.w;
        }
      }
#pragma unroll
      for (int h = 0; h < 8; h++) ew[hh + h][kk] = valid ? __expf(d[h] * 0.125f) : 0.f;
    }
    __syncthreads();

    // phase 2: denominators (float4 reads)
    {
      int h = tid >> 4, seg = tid & 15;
      float4 v0 = *reinterpret_cast<const float4*>(&ew[h][seg * 8]);
      float4 v1 = *reinterpret_cast<const float4*>(&ew[h][seg * 8 + 4]);
      float p = v0.x + v0.y + v0.z + v0.w + v1.x + v1.y + v1.z + v1.w;
#pragma unroll
      for (int off = 8; off > 0; off >>= 1) p += __shfl_down_sync(0xffffffffu, p, off);
      if (seg == 0) denom[h] += p;
    }

    // phase 3: AV accumulation, vectorized (ew float4 warp-broadcast)
    for (int k4 = 0; k4 < 128; k4 += 4) {
      float4 e0 = *reinterpret_cast<const float4*>(&ew[g][k4]);
      float4 e1 = *reinterpret_cast<const float4*>(&ew[g + 4][k4]);
      float4 e2 = *reinterpret_cast<const float4*>(&ew[g + 8][k4]);
      float4 e3 = *reinterpret_cast<const float4*>(&ew[g + 12][k4]);
      float kv0 = Ks[k4 + 0][c];
      float kv1 = Ks[k4 + 1][c];
      float kv2 = Ks[k4 + 2][c];
      float kv3 = Ks[k4 + 3][c];
      acc0 += e0.x * kv0 + e0.y * kv1 + e0.z * kv2 + e0.w * kv3;
      acc1 += e1.x * kv0 + e1.y * kv1 + e1.z * kv2 + e1.w * kv3;
      acc2 += e2.x * kv0 + e2.y * kv1 + e2.z * kv2 + e2.w * kv3;
      acc3 += e3.x * kv0 + e3.y * kv1 + e3.z * kv2 + e3.w * kv3;
    }
  }
  __syncthreads();

  g_ao[(size_t)s * 1024 + (g) * 64 + c] = acc0 / denom[g];
  g_ao[(size_t)s * 1024 + (g + 4) * 64 + c] = acc1 / denom[g + 4];
  g_ao[(size_t)s * 1024 + (g + 8) * 64 + c] = acc2 / denom[g + 8];
  g_ao[(size_t)s * 1024 + (g + 12) * 64 + c] = acc3 / denom[g + 12];
}

// ---------------------------- launcher ----------------------------------
extern "C" void kernel_launch(void* const* d_in, const int* in_sizes, int n_in,
                              void* d_out, int out_size) {
  (void)in_sizes; (void)n_in; (void)out_size;
  const float* x      = (const float*)d_in[0];
  const float* w_kva  = (const float*)d_in[1];
  const float* w_kvb  = (const float*)d_in[2];
  const float* w_za   = (const float*)d_in[3];
  const float* w_zb   = (const float*)d_in[4];
  const float* b_a    = (const float*)d_in[5];
  const float* b_b    = (const float*)d_in[6];
  const float* w_dq   = (const float*)d_in[7];
  const float* w_iuq  = (const float*)d_in[8];
  const float* w_w    = (const float*)d_in[9];
  const float* w_k    = (const float*)d_in[10];
  const float* w_uq   = (const float*)d_in[11];
  const float* o_down = (const float*)d_in[12];
  const float* o_up   = (const float*)d_in[13];
  const float* kvn_w  = (const float*)d_in[14];
  const float* kvn_b  = (const float*)d_in[15];
  const float* qn_w   = (const float*)d_in[16];
  const float* qn_b   = (const float*)d_in[17];
  const float* sink   = (const float*)d_in[18];
  float* out = (float*)d_out;

  void *p_ca, *p_cb, *p_za, *p_zb, *p_cq, *p_qi, *p_ko, *p_kp, *p_qf, *p_ao, *p_gb;
  cudaGetSymbolAddress(&p_ca, g_ca);
  cudaGetSymbolAddress(&p_cb, g_cb);
  cudaGetSymbolAddress(&p_za, g_za);
  cudaGetSymbolAddress(&p_zb, g_zb);
  cudaGetSymbolAddress(&p_cq, g_cq);
  cudaGetSymbolAddress(&p_qi, g_qi);
  cudaGetSymbolAddress(&p_ko, g_ko);
  cudaGetSymbolAddress(&p_kp, g_kp);
  cudaGetSymbolAddress(&p_qf, g_qf);
  cudaGetSymbolAddress(&p_ao, g_ao);
  cudaGetSymbolAddress(&p_gb, g_gb);

  auto grid2 = [](int M, int N) { return dim3((unsigned)(N / 128), (unsigned)(M / 128), 1u); };

  // chunk means first (feeds k_proj inside fused projections)
  kmean_kernel<<<(NC_CH * D_DIM + 255) / 256, 256>>>(x);

  // fused narrow projections
  ProjArgs pa;
  pa.A[0] = x;     pa.B[0] = w_kva; pa.Cc[0] = (float*)p_ca; pa.M[0] = S_LEN;
  pa.A[1] = x;     pa.B[1] = w_kvb; pa.Cc[1] = (float*)p_cb; pa.M[1] = S_LEN;
  pa.A[2] = x;     pa.B[2] = w_za;  pa.Cc[2] = (float*)p_za; pa.M[2] = S_LEN;
  pa.A[3] = x;     pa.B[3] = w_zb;  pa.Cc[3] = (float*)p_zb; pa.M[3] = S_LEN;
  pa.A[4] = (const float*)p_ko; pa.B[4] = w_k; pa.Cc[4] = (float*)p_kp; pa.M[4] = NC_CH;
  proj64_kernel<<<dim3(5, S_LEN / 128), 256>>>(pa);

  // hw = x @ w_w
  hw_kernel<<<S_LEN / 8, 256>>>(x, w_w);

  // c_q = x @ w_dq  (fp32 — feeds the discrete top-k path)
  sgemm_kernel<<<grid2(S_LEN, DC_N), 256>>>(x, w_dq, (float*)p_cq, D_DIM, D_DIM, DC_N, DC_N, 0, 0, 0);

  // chunk compression + LN(kc)
  compress_kernel<<<NC_CH, 64>>>(b_a, b_b, kvn_w, kvn_b);

  // indexer path (fp32 — discrete)
  sgemm_kernel<<<grid2(S_LEN, NHI_N * CI_N), 256>>>((const float*)p_cq, w_iuq, (float*)p_qi,
                                                    DC_N, DC_N, NHI_N * CI_N, NHI_N * CI_N, 0, 0, 0);
  iscore_kernel<<<S_LEN, 256>>>();
  topk_kernel<<<S_LEN, 512>>>();

  // q path (tensor bf16 3x — continuous), then LN + rope in-place
  tgemm_kernel<<<grid2(S_LEN, NH_N * C_DIM), 256>>>((const float*)p_cq, w_uq, (float*)p_qf,
                                                    DC_N, DC_N, NH_N * C_DIM, NH_N * C_DIM, 0, 0, 0);
  qln_rope_kernel<<<S_LEN, dim3(64, 16)>>>(qn_w, qn_b);

  // sparse attention over top-k compressed chunks
  attn_kernel<<<S_LEN, 256>>>(sink);

  // grouped o_down: ONE batched launch (z = group), tensor
  tgemm_kernel<<<dim3(DG_N / 128, S_LEN / 128, NG_N), 256>>>(
      (const float*)p_ao, o_down, (float*)p_gb,
      256, NH_N * C_DIM, DG_N, NG_N * DG_N,
      /*sA=*/256, /*sB=*/(long)256 * DG_N, /*sC=*/DG_N);

  // o_up (tensor)
  tgemm_kernel<<<grid2(S_LEN, D_DIM), 256>>>((const float*)p_gb, o_up, out,
                                             NG_N * DG_N, NG_N * DG_N, D_DIM, D_DIM, 0, 0, 0);
}